// round 1
// baseline (speedup 1.0000x reference)
#include <cuda_runtime.h>
#include <math.h>

#define LL 1024
#define NB 8
#define CC 1024
#define HH 16
#define HD 64
#define MM (LL*NB)          // 8192 rows (l*NB + n)
#define C3 (3*CC)           // 3072
#define NHH (NB*HH)         // 128
#define LOGIT_MAX 4.605170185988091f   // log(1/0.01)

// ---- scratch (device globals: allocation-free per harness rules) ----
__device__ float g_qkv[(size_t)MM * C3];      // 96 MB
__device__ float g_q[(size_t)NHH * LL * HD];  // 32 MB (normalized * logit scale)
__device__ float g_k[(size_t)NHH * LL * HD];  // 32 MB (normalized)
__device__ float g_v[(size_t)NHH * LL * HD];  // 32 MB
__device__ float g_o[(size_t)MM * CC];        // 32 MB (attention out, (l,n,c) layout)

// ============================================================
// SGEMM (NT): C[m][n] = sum_k A[m][k]*B[n][k] + bias[n]
// BM=BN=128, BK=16, 256 threads, 8x8 register tile.
// M, K, Ncols all multiples of tile sizes (8192/1024/{3072,1024}).
// ============================================================
__global__ __launch_bounds__(256, 2)
void sgemm_nt_bias(const float* __restrict__ A, const float* __restrict__ B,
                   const float* __restrict__ bias, float* __restrict__ C,
                   int K, int Ncols) {
    __shared__ float As[16][128];
    __shared__ float Bs[16][128];
    const int t  = threadIdx.x;
    const int m0 = blockIdx.y * 128;
    const int n0 = blockIdx.x * 128;
    const int lr = t >> 2;        // 0..63 (row within half-tile)
    const int lq = t & 3;         // 0..3  (k-quad)
    const int tx = t & 15;
    const int ty = t >> 4;
    float acc[8][8] = {};
    const float* Ap = A + (size_t)(m0 + lr) * K + lq * 4;
    const float* Bp = B + (size_t)(n0 + lr) * K + lq * 4;

    for (int k0 = 0; k0 < K; k0 += 16) {
        #pragma unroll
        for (int p = 0; p < 2; p++) {
            float4 va = *reinterpret_cast<const float4*>(Ap + (size_t)p * 64 * K + k0);
            As[lq*4+0][lr + p*64] = va.x;
            As[lq*4+1][lr + p*64] = va.y;
            As[lq*4+2][lr + p*64] = va.z;
            As[lq*4+3][lr + p*64] = va.w;
            float4 vb = *reinterpret_cast<const float4*>(Bp + (size_t)p * 64 * K + k0);
            Bs[lq*4+0][lr + p*64] = vb.x;
            Bs[lq*4+1][lr + p*64] = vb.y;
            Bs[lq*4+2][lr + p*64] = vb.z;
            Bs[lq*4+3][lr + p*64] = vb.w;
        }
        __syncthreads();
        #pragma unroll
        for (int k = 0; k < 16; k++) {
            float ra[8], rb[8];
            *reinterpret_cast<float4*>(&ra[0]) = *reinterpret_cast<const float4*>(&As[k][ty*8]);
            *reinterpret_cast<float4*>(&ra[4]) = *reinterpret_cast<const float4*>(&As[k][ty*8+4]);
            *reinterpret_cast<float4*>(&rb[0]) = *reinterpret_cast<const float4*>(&Bs[k][tx*8]);
            *reinterpret_cast<float4*>(&rb[4]) = *reinterpret_cast<const float4*>(&Bs[k][tx*8+4]);
            #pragma unroll
            for (int i = 0; i < 8; i++)
                #pragma unroll
                for (int j = 0; j < 8; j++)
                    acc[i][j] += ra[i] * rb[j];
        }
        __syncthreads();
    }
    #pragma unroll
    for (int i = 0; i < 8; i++) {
        const int m = m0 + ty*8 + i;
        #pragma unroll
        for (int j4 = 0; j4 < 2; j4++) {
            float4 bv = *reinterpret_cast<const float4*>(&bias[n0 + tx*8 + j4*4]);
            float4 o;
            o.x = acc[i][j4*4+0] + bv.x;
            o.y = acc[i][j4*4+1] + bv.y;
            o.z = acc[i][j4*4+2] + bv.z;
            o.w = acc[i][j4*4+3] + bv.w;
            *reinterpret_cast<float4*>(&C[(size_t)m * Ncols + n0 + tx*8 + j4*4]) = o;
        }
    }
}

// ============================================================
// Normalize q,k rows (L2 over head dim, eps=1e-12), fold logit scale
// into q, scatter q/k/v from (m, 3C) into (nh, l, d) layout.
// One warp per 64-element row. 3*128*1024 = 393216 warps.
// ============================================================
__global__ __launch_bounds__(256)
void norm_scatter_kernel(const float* __restrict__ logit_scale) {
    const int warp = (blockIdx.x * blockDim.x + threadIdx.x) >> 5;
    const int lane = threadIdx.x & 31;
    const int tsel = warp / (NHH * LL);          // 0=q 1=k 2=v
    const int rr   = warp - tsel * (NHH * LL);
    const int nh   = rr >> 10;
    const int l    = rr & 1023;
    const int n    = nh >> 4;
    const int h    = nh & 15;
    const size_t src = (size_t)(l * NB + n) * C3 + (size_t)tsel * CC + h * HD;
    float v0 = g_qkv[src + lane];
    float v1 = g_qkv[src + lane + 32];
    if (tsel < 2) {
        float s = v0*v0 + v1*v1;
        #pragma unroll
        for (int o = 16; o > 0; o >>= 1) s += __shfl_xor_sync(0xffffffffu, s, o);
        float inv = 1.0f / fmaxf(sqrtf(s), 1e-12f);
        if (tsel == 0) inv *= expf(fminf(logit_scale[h], LOGIT_MAX));
        v0 *= inv; v1 *= inv;
    }
    float* dst = (tsel == 0) ? g_q : ((tsel == 1) ? g_k : g_v);
    const size_t o = ((size_t)nh * LL + l) * HD;
    dst[o + lane]      = v0;
    dst[o + lane + 32] = v1;
}

// ============================================================
// Flash attention, fp32. One block = one (nh, 64-query tile).
// 128 threads: tx=t&15 (covers kc/d cols strided by 16), ty=t>>4 (8 q-rows each).
// Smem: QsT/KsT transposed [d][row] stride 65 (conflict-free scalar reads),
//       Vs natural [kc][d], Ps natural [qr][kc] stride 65.
// ============================================================
#define SSTR 65
#define FLASH_SMEM ((3*64*SSTR + 64*64) * (int)sizeof(float))   // 66304 B

__global__ __launch_bounds__(128)
void flash_attn_kernel(const float* __restrict__ head_scale) {
    extern __shared__ float smf[];
    float* QsT = smf;
    float* KsT = smf + 64*SSTR;
    float* Vs  = smf + 2*64*SSTR;
    float* Ps  = smf + 2*64*SSTR + 64*64;

    const int t  = threadIdx.x;
    const int tx = t & 15;
    const int ty = t >> 4;            // 0..7
    const int nh = blockIdx.y;
    const int qt = blockIdx.x;
    const float* Qg = g_q + ((size_t)nh * LL + qt * 64) * HD;
    const float* Kg = g_k + (size_t)nh * LL * HD;
    const float* Vg = g_v + (size_t)nh * LL * HD;

    // load Q tile transposed
    for (int idx = t; idx < 64*16; idx += 128) {
        int r = idx >> 4, c4 = (idx & 15) << 2;
        float4 v = *reinterpret_cast<const float4*>(&Qg[r*64 + c4]);
        QsT[(c4+0)*SSTR + r] = v.x;
        QsT[(c4+1)*SSTR + r] = v.y;
        QsT[(c4+2)*SSTR + r] = v.z;
        QsT[(c4+3)*SSTR + r] = v.w;
    }

    float acc[8][4] = {};
    float mi[8], li[8];
    #pragma unroll
    for (int r = 0; r < 8; r++) { mi[r] = -1e30f; li[r] = 0.0f; }

    for (int kt = 0; kt < 16; kt++) {
        const float* Kt = Kg + kt * 64 * 64;
        const float* Vt = Vg + kt * 64 * 64;
        for (int idx = t; idx < 64*16; idx += 128) {
            int r = idx >> 4, c4 = (idx & 15) << 2;
            float4 v = *reinterpret_cast<const float4*>(&Kt[r*64 + c4]);
            KsT[(c4+0)*SSTR + r] = v.x;
            KsT[(c4+1)*SSTR + r] = v.y;
            KsT[(c4+2)*SSTR + r] = v.z;
            KsT[(c4+3)*SSTR + r] = v.w;
            *reinterpret_cast<float4*>(&Vs[r*64 + c4]) =
                *reinterpret_cast<const float4*>(&Vt[r*64 + c4]);
        }
        __syncthreads();

        // S[r][c] over rows ty*8+r, cols tx + 16*c
        float s[8][4] = {};
        #pragma unroll 4
        for (int d = 0; d < 64; d++) {
            float kv[4], qv[8];
            #pragma unroll
            for (int c = 0; c < 4; c++) kv[c] = KsT[d*SSTR + tx + 16*c];
            #pragma unroll
            for (int r = 0; r < 8; r++) qv[r] = QsT[d*SSTR + ty*8 + r];
            #pragma unroll
            for (int r = 0; r < 8; r++)
                #pragma unroll
                for (int c = 0; c < 4; c++)
                    s[r][c] += qv[r] * kv[c];
        }

        // online softmax (rows shared across 16 tx-lanes; xor-reduce masks 1,2,4,8)
        #pragma unroll
        for (int r = 0; r < 8; r++) {
            float rm = fmaxf(fmaxf(s[r][0], s[r][1]), fmaxf(s[r][2], s[r][3]));
            rm = fmaxf(rm, __shfl_xor_sync(0xffffffffu, rm, 1));
            rm = fmaxf(rm, __shfl_xor_sync(0xffffffffu, rm, 2));
            rm = fmaxf(rm, __shfl_xor_sync(0xffffffffu, rm, 4));
            rm = fmaxf(rm, __shfl_xor_sync(0xffffffffu, rm, 8));
            float mnew = fmaxf(mi[r], rm);
            float corr = __expf(mi[r] - mnew);
            float rs = 0.0f;
            #pragma unroll
            for (int c = 0; c < 4; c++) {
                float p = __expf(s[r][c] - mnew);
                s[r][c] = p;
                rs += p;
            }
            rs += __shfl_xor_sync(0xffffffffu, rs, 1);
            rs += __shfl_xor_sync(0xffffffffu, rs, 2);
            rs += __shfl_xor_sync(0xffffffffu, rs, 4);
            rs += __shfl_xor_sync(0xffffffffu, rs, 8);
            li[r] = li[r] * corr + rs;
            mi[r] = mnew;
            #pragma unroll
            for (int c = 0; c < 4; c++) acc[r][c] *= corr;
            #pragma unroll
            for (int c = 0; c < 4; c++)
                Ps[(ty*8 + r)*SSTR + tx + 16*c] = s[r][c];
        }
        __syncthreads();

        // acc[r][c] += sum_kc P[qr][kc] * V[kc][tx+16c]
        #pragma unroll 4
        for (int kc = 0; kc < 64; kc++) {
            float vv[4], pv[8];
            #pragma unroll
            for (int c = 0; c < 4; c++) vv[c] = Vs[kc*64 + tx + 16*c];
            #pragma unroll
            for (int r = 0; r < 8; r++) pv[r] = Ps[(ty*8 + r)*SSTR + kc];
            #pragma unroll
            for (int r = 0; r < 8; r++)
                #pragma unroll
                for (int c = 0; c < 4; c++)
                    acc[r][c] += pv[r] * vv[c];
        }
        __syncthreads();
    }

    // epilogue: /l_i, * head_scale, write (l, n, h*64+d)
    const int h = nh & 15;
    const int n = nh >> 4;
    const float hs = head_scale[h];
    #pragma unroll
    for (int r = 0; r < 8; r++) {
        const int l = qt*64 + ty*8 + r;
        const float invl = hs / li[r];
        const size_t off = ((size_t)l * NB + n) * CC + h * HD + tx;
        #pragma unroll
        for (int c = 0; c < 4; c++)
            g_o[off + 16*c] = acc[r][c] * invl;
    }
}

// ============================================================
extern "C" void kernel_launch(void* const* d_in, const int* in_sizes, int n_in,
                              void* d_out, int out_size) {
    const float* x           = (const float*)d_in[0];
    const float* w_in        = (const float*)d_in[1];
    const float* b_in        = (const float*)d_in[2];
    const float* logit_scale = (const float*)d_in[3];
    const float* head_scale  = (const float*)d_in[4];
    const float* out_w       = (const float*)d_in[5];
    const float* out_b       = (const float*)d_in[6];
    float* out = (float*)d_out;

    float *qkv_p, *o_p;
    cudaGetSymbolAddress((void**)&qkv_p, g_qkv);
    cudaGetSymbolAddress((void**)&o_p, g_o);

    cudaFuncSetAttribute(flash_attn_kernel,
                         cudaFuncAttributeMaxDynamicSharedMemorySize, FLASH_SMEM);

    // 1) qkv = x @ W^T + b
    sgemm_nt_bias<<<dim3(C3/128, MM/128), 256>>>(x, w_in, b_in, qkv_p, CC, C3);
    // 2) normalize q,k (fold logit scale into q), scatter to head layout
    norm_scatter_kernel<<<(3*NHH*LL)/8, 256>>>(logit_scale);
    // 3) flash attention per (nh, q-tile)
    flash_attn_kernel<<<dim3(LL/64, NHH), 128, FLASH_SMEM>>>(head_scale);
    // 4) out = o @ out_w^T + out_b
    sgemm_nt_bias<<<dim3(CC/128, MM/128), 256>>>(o_p, out_w, out_b, out, CC, CC);
}

// round 3
// speedup vs baseline: 1.4945x; 1.4945x over previous
#include <cuda_runtime.h>
#include <math.h>
#include <stdint.h>

#define LL 1024
#define NB 8
#define CC 1024
#define HH 16
#define HD 64
#define MM (LL*NB)          // 8192
#define C3 (3*CC)           // 3072
#define NHH (NB*HH)         // 128
#define LOGIT_MAX 4.605170185988091f

// ---- scratch (device globals) ----
__device__ float g_qkv[(size_t)MM * C3];      // 96 MB
__device__ float g_q[(size_t)NHH * LL * HD];
__device__ float g_k[(size_t)NHH * LL * HD];
__device__ float g_v[(size_t)NHH * LL * HD];
__device__ float g_o[(size_t)MM * CC];

__device__ __forceinline__ float tf32r(float x) {
    uint32_t u;
    asm("cvt.rna.tf32.f32 %0, %1;" : "=r"(u) : "f"(x));
    return __uint_as_float(u);
}

__device__ __forceinline__ void mma_tf32_16x8x8(float* d, const uint32_t* a, const uint32_t* b) {
    asm volatile(
        "mma.sync.aligned.m16n8k8.row.col.f32.tf32.tf32.f32 "
        "{%0,%1,%2,%3}, {%4,%5,%6,%7}, {%8,%9}, {%0,%1,%2,%3};\n"
        : "+f"(d[0]), "+f"(d[1]), "+f"(d[2]), "+f"(d[3])
        : "r"(a[0]), "r"(a[1]), "r"(a[2]), "r"(a[3]), "r"(b[0]), "r"(b[1]));
}

// ============================================================
// tf32 mma.sync GEMM (NT): C[m][n] = sum_k A[m][k]*B[n][k] + bias[n]
// BM=BN=128, BK=16, 256 threads (8 warps as 2x4), warp tile 64x32.
// Smem [k][row] padded stride 132, tf32-rounded at fill.
// ============================================================
#define SA 132
__global__ __launch_bounds__(256, 2)
void gemm_tf32_mma(const float* __restrict__ A, const float* __restrict__ B,
                   const float* __restrict__ bias, float* __restrict__ C,
                   int K, int Ncols) {
    __shared__ float As[16*SA];
    __shared__ float Bs[16*SA];
    const int t  = threadIdx.x;
    const int m0 = blockIdx.y * 128;
    const int n0 = blockIdx.x * 128;
    const int lr = t >> 2;        // 0..63
    const int lq = t & 3;         // 0..3
    const int wid  = t >> 5;
    const int lane = t & 31;
    const int g  = lane >> 2;     // 0..7
    const int kq = lane & 3;      // 0..3
    const int wm = (wid >> 2) * 64;   // warp m-offset (0/64)
    const int wn = (wid & 3) * 32;    // warp n-offset (0/32/64/96)

    float d[4][4][4] = {};
    const float* Ap = A + (size_t)(m0 + lr) * K + lq * 4;
    const float* Bp = B + (size_t)(n0 + lr) * K + lq * 4;

    for (int k0 = 0; k0 < K; k0 += 16) {
        #pragma unroll
        for (int p = 0; p < 2; p++) {
            float4 va = *reinterpret_cast<const float4*>(Ap + (size_t)p * 64 * K + k0);
            As[(lq*4+0)*SA + lr + p*64] = tf32r(va.x);
            As[(lq*4+1)*SA + lr + p*64] = tf32r(va.y);
            As[(lq*4+2)*SA + lr + p*64] = tf32r(va.z);
            As[(lq*4+3)*SA + lr + p*64] = tf32r(va.w);
            float4 vb = *reinterpret_cast<const float4*>(Bp + (size_t)p * 64 * K + k0);
            Bs[(lq*4+0)*SA + lr + p*64] = tf32r(vb.x);
            Bs[(lq*4+1)*SA + lr + p*64] = tf32r(vb.y);
            Bs[(lq*4+2)*SA + lr + p*64] = tf32r(vb.z);
            Bs[(lq*4+3)*SA + lr + p*64] = tf32r(vb.w);
        }
        __syncthreads();
        #pragma unroll
        for (int s = 0; s < 2; s++) {
            const int kb = s * 8;
            uint32_t a[4][4], b[4][2];
            #pragma unroll
            for (int ti = 0; ti < 4; ti++) {
                const int mr = wm + ti*16 + g;
                a[ti][0] = __float_as_uint(As[(kb+kq)*SA   + mr]);
                a[ti][1] = __float_as_uint(As[(kb+kq)*SA   + mr + 8]);
                a[ti][2] = __float_as_uint(As[(kb+kq+4)*SA + mr]);
                a[ti][3] = __float_as_uint(As[(kb+kq+4)*SA + mr + 8]);
            }
            #pragma unroll
            for (int j = 0; j < 4; j++) {
                const int nc = wn + j*8 + g;
                b[j][0] = __float_as_uint(Bs[(kb+kq)*SA   + nc]);
                b[j][1] = __float_as_uint(Bs[(kb+kq+4)*SA + nc]);
            }
            #pragma unroll
            for (int ti = 0; ti < 4; ti++)
                #pragma unroll
                for (int j = 0; j < 4; j++)
                    mma_tf32_16x8x8(d[ti][j], a[ti], b[j]);
        }
        __syncthreads();
    }

    // epilogue: d[ti][j]: rows wm+ti*16+g (+8), cols wn+j*8+2*kq (+1)
    #pragma unroll
    for (int ti = 0; ti < 4; ti++) {
        const int r0 = m0 + wm + ti*16 + g;
        #pragma unroll
        for (int j = 0; j < 4; j++) {
            const int c0 = n0 + wn + j*8 + 2*kq;
            const float bx = bias[c0], by = bias[c0+1];
            float2 lo, hi;
            lo.x = d[ti][j][0] + bx; lo.y = d[ti][j][1] + by;
            hi.x = d[ti][j][2] + bx; hi.y = d[ti][j][3] + by;
            *reinterpret_cast<float2*>(&C[(size_t)r0 * Ncols + c0]) = lo;
            *reinterpret_cast<float2*>(&C[(size_t)(r0+8) * Ncols + c0]) = hi;
        }
    }
}

// ============================================================
// Normalize q,k rows (L2 over head dim), fold logit scale into q,
// scatter q/k/v from (m, 3C) into (nh, l, d) layout. Warp per row.
// ============================================================
__global__ __launch_bounds__(256)
void norm_scatter_kernel(const float* __restrict__ logit_scale) {
    const int warp = (blockIdx.x * blockDim.x + threadIdx.x) >> 5;
    const int lane = threadIdx.x & 31;
    const int tsel = warp / (NHH * LL);
    const int rr   = warp - tsel * (NHH * LL);
    const int nh   = rr >> 10;
    const int l    = rr & 1023;
    const int n    = nh >> 4;
    const int h    = nh & 15;
    const size_t src = (size_t)(l * NB + n) * C3 + (size_t)tsel * CC + h * HD;
    float v0 = g_qkv[src + lane];
    float v1 = g_qkv[src + lane + 32];
    if (tsel < 2) {
        float s = v0*v0 + v1*v1;
        #pragma unroll
        for (int o = 16; o > 0; o >>= 1) s += __shfl_xor_sync(0xffffffffu, s, o);
        float inv = 1.0f / fmaxf(sqrtf(s), 1e-12f);
        if (tsel == 0) inv *= expf(fminf(logit_scale[h], LOGIT_MAX));
        v0 *= inv; v1 *= inv;
    }
    float* dst = (tsel == 0) ? g_q : ((tsel == 1) ? g_k : g_v);
    const size_t o = ((size_t)nh * LL + l) * HD;
    dst[o + lane]      = v0;
    dst[o + lane + 32] = v1;
}

// ============================================================
// Flash attention, fp32 (unchanged).
// ============================================================
#define SSTR 65
#define FLASH_SMEM ((3*64*SSTR + 64*64) * (int)sizeof(float))

__global__ __launch_bounds__(128)
void flash_attn_kernel(const float* __restrict__ head_scale) {
    extern __shared__ float smf[];
    float* QsT = smf;
    float* KsT = smf + 64*SSTR;
    float* Vs  = smf + 2*64*SSTR;
    float* Ps  = smf + 2*64*SSTR + 64*64;

    const int t  = threadIdx.x;
    const int tx = t & 15;
    const int ty = t >> 4;
    const int nh = blockIdx.y;
    const int qt = blockIdx.x;
    const float* Qg = g_q + ((size_t)nh * LL + qt * 64) * HD;
    const float* Kg = g_k + (size_t)nh * LL * HD;
    const float* Vg = g_v + (size_t)nh * LL * HD;

    for (int idx = t; idx < 64*16; idx += 128) {
        int r = idx >> 4, c4 = (idx & 15) << 2;
        float4 v = *reinterpret_cast<const float4*>(&Qg[r*64 + c4]);
        QsT[(c4+0)*SSTR + r] = v.x;
        QsT[(c4+1)*SSTR + r] = v.y;
        QsT[(c4+2)*SSTR + r] = v.z;
        QsT[(c4+3)*SSTR + r] = v.w;
    }

    float acc[8][4] = {};
    float mi[8], li[8];
    #pragma unroll
    for (int r = 0; r < 8; r++) { mi[r] = -1e30f; li[r] = 0.0f; }

    for (int kt = 0; kt < 16; kt++) {
        const float* Kt = Kg + kt * 64 * 64;
        const float* Vt = Vg + kt * 64 * 64;
        for (int idx = t; idx < 64*16; idx += 128) {
            int r = idx >> 4, c4 = (idx & 15) << 2;
            float4 v = *reinterpret_cast<const float4*>(&Kt[r*64 + c4]);
            KsT[(c4+0)*SSTR + r] = v.x;
            KsT[(c4+1)*SSTR + r] = v.y;
            KsT[(c4+2)*SSTR + r] = v.z;
            KsT[(c4+3)*SSTR + r] = v.w;
            *reinterpret_cast<float4*>(&Vs[r*64 + c4]) =
                *reinterpret_cast<const float4*>(&Vt[r*64 + c4]);
        }
        __syncthreads();

        float s[8][4] = {};
        #pragma unroll 4
        for (int d = 0; d < 64; d++) {
            float kv[4], qv[8];
            #pragma unroll
            for (int c = 0; c < 4; c++) kv[c] = KsT[d*SSTR + tx + 16*c];
            #pragma unroll
            for (int r = 0; r < 8; r++) qv[r] = QsT[d*SSTR + ty*8 + r];
            #pragma unroll
            for (int r = 0; r < 8; r++)
                #pragma unroll
                for (int c = 0; c < 4; c++)
                    s[r][c] += qv[r] * kv[c];
        }

        #pragma unroll
        for (int r = 0; r < 8; r++) {
            float rm = fmaxf(fmaxf(s[r][0], s[r][1]), fmaxf(s[r][2], s[r][3]));
            rm = fmaxf(rm, __shfl_xor_sync(0xffffffffu, rm, 1));
            rm = fmaxf(rm, __shfl_xor_sync(0xffffffffu, rm, 2));
            rm = fmaxf(rm, __shfl_xor_sync(0xffffffffu, rm, 4));
            rm = fmaxf(rm, __shfl_xor_sync(0xffffffffu, rm, 8));
            float mnew = fmaxf(mi[r], rm);
            float corr = __expf(mi[r] - mnew);
            float rs = 0.0f;
            #pragma unroll
            for (int c = 0; c < 4; c++) {
                float p = __expf(s[r][c] - mnew);
                s[r][c] = p;
                rs += p;
            }
            rs += __shfl_xor_sync(0xffffffffu, rs, 1);
            rs += __shfl_xor_sync(0xffffffffu, rs, 2);
            rs += __shfl_xor_sync(0xffffffffu, rs, 4);
            rs += __shfl_xor_sync(0xffffffffu, rs, 8);
            li[r] = li[r] * corr + rs;
            mi[r] = mnew;
            #pragma unroll
            for (int c = 0; c < 4; c++) acc[r][c] *= corr;
            #pragma unroll
            for (int c = 0; c < 4; c++)
                Ps[(ty*8 + r)*SSTR + tx + 16*c] = s[r][c];
        }
        __syncthreads();

        #pragma unroll 4
        for (int kc = 0; kc < 64; kc++) {
            float vv[4], pv[8];
            #pragma unroll
            for (int c = 0; c < 4; c++) vv[c] = Vs[kc*64 + tx + 16*c];
            #pragma unroll
            for (int r = 0; r < 8; r++) pv[r] = Ps[(ty*8 + r)*SSTR + kc];
            #pragma unroll
            for (int r = 0; r < 8; r++)
                #pragma unroll
                for (int c = 0; c < 4; c++)
                    acc[r][c] += pv[r] * vv[c];
        }
        __syncthreads();
    }

    const int h = nh & 15;
    const int n = nh >> 4;
    const float hs = head_scale[h];
    #pragma unroll
    for (int r = 0; r < 8; r++) {
        const int l = qt*64 + ty*8 + r;
        const float invl = hs / li[r];
        const size_t off = ((size_t)l * NB + n) * CC + h * HD + tx;
        #pragma unroll
        for (int c = 0; c < 4; c++)
            g_o[off + 16*c] = acc[r][c] * invl;
    }
}

// ============================================================
extern "C" void kernel_launch(void* const* d_in, const int* in_sizes, int n_in,
                              void* d_out, int out_size) {
    const float* x           = (const float*)d_in[0];
    const float* w_in        = (const float*)d_in[1];
    const float* b_in        = (const float*)d_in[2];
    const float* logit_scale = (const float*)d_in[3];
    const float* head_scale  = (const float*)d_in[4];
    const float* out_w       = (const float*)d_in[5];
    const float* out_b       = (const float*)d_in[6];
    float* out = (float*)d_out;

    float *qkv_p, *o_p;
    cudaGetSymbolAddress((void**)&qkv_p, g_qkv);
    cudaGetSymbolAddress((void**)&o_p, g_o);

    cudaFuncSetAttribute(flash_attn_kernel,
                         cudaFuncAttributeMaxDynamicSharedMemorySize, FLASH_SMEM);

    // 1) qkv = x @ W^T + b   (tf32 mma.sync)
    gemm_tf32_mma<<<dim3(C3/128, MM/128), 256>>>(x, w_in, b_in, qkv_p, CC, C3);
    // 2) normalize + scatter
    norm_scatter_kernel<<<(3*NHH*LL)/8, 256>>>(logit_scale);
    // 3) flash attention (fp32)
    flash_attn_kernel<<<dim3(LL/64, NHH), 128, FLASH_SMEM>>>(head_scale);
    // 4) out = o @ out_w^T + out_b  (tf32 mma.sync)
    gemm_tf32_mma<<<dim3(CC/128, MM/128), 256>>>(o_p, out_w, out_b, out, CC, CC);
}

// round 4
// speedup vs baseline: 1.7226x; 1.1526x over previous
#include <cuda_runtime.h>
#include <math.h>
#include <stdint.h>

#define LL 1024
#define NB 8
#define CC 1024
#define HH 16
#define HD 64
#define MM (LL*NB)          // 8192
#define C3 (3*CC)           // 3072
#define NHH (NB*HH)         // 128
#define LOGIT_MAX 4.605170185988091f

// ---- scratch (device globals) ----
__device__ float g_qkv[(size_t)MM * C3];
__device__ float g_q[(size_t)NHH * LL * HD];
__device__ float g_k[(size_t)NHH * LL * HD];
__device__ float g_v[(size_t)NHH * LL * HD];
__device__ float g_o[(size_t)MM * CC];

__device__ __forceinline__ float tf32r(float x) {
    uint32_t u;
    asm("cvt.rna.tf32.f32 %0, %1;" : "=r"(u) : "f"(x));
    return __uint_as_float(u);
}

__device__ __forceinline__ void mma_tf32_16x8x8(float* d, const uint32_t* a, const uint32_t* b) {
    asm volatile(
        "mma.sync.aligned.m16n8k8.row.col.f32.tf32.tf32.f32 "
        "{%0,%1,%2,%3}, {%4,%5,%6,%7}, {%8,%9}, {%0,%1,%2,%3};\n"
        : "+f"(d[0]), "+f"(d[1]), "+f"(d[2]), "+f"(d[3])
        : "r"(a[0]), "r"(a[1]), "r"(a[2]), "r"(a[3]), "r"(b[0]), "r"(b[1]));
}

// ============================================================
// tf32 mma.sync GEMM (NT): unchanged from R3 (passing).
// ============================================================
#define SA 132
__global__ __launch_bounds__(256, 2)
void gemm_tf32_mma(const float* __restrict__ A, const float* __restrict__ B,
                   const float* __restrict__ bias, float* __restrict__ C,
                   int K, int Ncols) {
    __shared__ float As[16*SA];
    __shared__ float Bs[16*SA];
    const int t  = threadIdx.x;
    const int m0 = blockIdx.y * 128;
    const int n0 = blockIdx.x * 128;
    const int lr = t >> 2;
    const int lq = t & 3;
    const int wid  = t >> 5;
    const int lane = t & 31;
    const int g  = lane >> 2;
    const int kq = lane & 3;
    const int wm = (wid >> 2) * 64;
    const int wn = (wid & 3) * 32;

    float d[4][4][4] = {};
    const float* Ap = A + (size_t)(m0 + lr) * K + lq * 4;
    const float* Bp = B + (size_t)(n0 + lr) * K + lq * 4;

    for (int k0 = 0; k0 < K; k0 += 16) {
        #pragma unroll
        for (int p = 0; p < 2; p++) {
            float4 va = *reinterpret_cast<const float4*>(Ap + (size_t)p * 64 * K + k0);
            As[(lq*4+0)*SA + lr + p*64] = tf32r(va.x);
            As[(lq*4+1)*SA + lr + p*64] = tf32r(va.y);
            As[(lq*4+2)*SA + lr + p*64] = tf32r(va.z);
            As[(lq*4+3)*SA + lr + p*64] = tf32r(va.w);
            float4 vb = *reinterpret_cast<const float4*>(Bp + (size_t)p * 64 * K + k0);
            Bs[(lq*4+0)*SA + lr + p*64] = tf32r(vb.x);
            Bs[(lq*4+1)*SA + lr + p*64] = tf32r(vb.y);
            Bs[(lq*4+2)*SA + lr + p*64] = tf32r(vb.z);
            Bs[(lq*4+3)*SA + lr + p*64] = tf32r(vb.w);
        }
        __syncthreads();
        #pragma unroll
        for (int s = 0; s < 2; s++) {
            const int kb = s * 8;
            uint32_t a[4][4], b[4][2];
            #pragma unroll
            for (int ti = 0; ti < 4; ti++) {
                const int mr = wm + ti*16 + g;
                a[ti][0] = __float_as_uint(As[(kb+kq)*SA   + mr]);
                a[ti][1] = __float_as_uint(As[(kb+kq)*SA   + mr + 8]);
                a[ti][2] = __float_as_uint(As[(kb+kq+4)*SA + mr]);
                a[ti][3] = __float_as_uint(As[(kb+kq+4)*SA + mr + 8]);
            }
            #pragma unroll
            for (int j = 0; j < 4; j++) {
                const int nc = wn + j*8 + g;
                b[j][0] = __float_as_uint(Bs[(kb+kq)*SA   + nc]);
                b[j][1] = __float_as_uint(Bs[(kb+kq+4)*SA + nc]);
            }
            #pragma unroll
            for (int ti = 0; ti < 4; ti++)
                #pragma unroll
                for (int j = 0; j < 4; j++)
                    mma_tf32_16x8x8(d[ti][j], a[ti], b[j]);
        }
        __syncthreads();
    }

    #pragma unroll
    for (int ti = 0; ti < 4; ti++) {
        const int r0 = m0 + wm + ti*16 + g;
        #pragma unroll
        for (int j = 0; j < 4; j++) {
            const int c0 = n0 + wn + j*8 + 2*kq;
            const float bx = bias[c0], by = bias[c0+1];
            float2 lo, hi;
            lo.x = d[ti][j][0] + bx; lo.y = d[ti][j][1] + by;
            hi.x = d[ti][j][2] + bx; hi.y = d[ti][j][3] + by;
            *reinterpret_cast<float2*>(&C[(size_t)r0 * Ncols + c0]) = lo;
            *reinterpret_cast<float2*>(&C[(size_t)(r0+8) * Ncols + c0]) = hi;
        }
    }
}

// ============================================================
// Normalize + scatter (unchanged).
// ============================================================
__global__ __launch_bounds__(256)
void norm_scatter_kernel(const float* __restrict__ logit_scale) {
    const int warp = (blockIdx.x * blockDim.x + threadIdx.x) >> 5;
    const int lane = threadIdx.x & 31;
    const int tsel = warp / (NHH * LL);
    const int rr   = warp - tsel * (NHH * LL);
    const int nh   = rr >> 10;
    const int l    = rr & 1023;
    const int n    = nh >> 4;
    const int h    = nh & 15;
    const size_t src = (size_t)(l * NB + n) * C3 + (size_t)tsel * CC + h * HD;
    float v0 = g_qkv[src + lane];
    float v1 = g_qkv[src + lane + 32];
    if (tsel < 2) {
        float s = v0*v0 + v1*v1;
        #pragma unroll
        for (int o = 16; o > 0; o >>= 1) s += __shfl_xor_sync(0xffffffffu, s, o);
        float inv = 1.0f / fmaxf(sqrtf(s), 1e-12f);
        if (tsel == 0) inv *= expf(fminf(logit_scale[h], LOGIT_MAX));
        v0 *= inv; v1 *= inv;
    }
    float* dst = (tsel == 0) ? g_q : ((tsel == 1) ? g_k : g_v);
    const size_t o = ((size_t)nh * LL + l) * HD;
    dst[o + lane]      = v0;
    dst[o + lane + 32] = v1;
}

// ============================================================
// Flash attention with tf32 mma.sync.
// Block = (nh, 64-query tile), 4 warps; warp w owns q-rows w*16..w*16+15.
// QK^T: 3xTF32 (hi/lo split) -> fp32-class logits. PV: single tf32.
// Smem: Qs/Ks hi-lo interleaved float2 [row][2*d] stride 132;
//       Vs [key][d] stride 72; Ps [qrow][key] stride 72.
// ============================================================
#define QKSTR 132
#define VSTR  72
#define PSTR  72
#define FL_Q 0
#define FL_K (64*QKSTR)
#define FL_V (2*64*QKSTR)
#define FL_P (2*64*QKSTR + 64*VSTR)
#define FLASH_SMEM ((2*64*QKSTR + 64*VSTR + 64*PSTR) * (int)sizeof(float))  // 104448

__global__ __launch_bounds__(128, 2)
void flash_attn_mma(const float* __restrict__ head_scale) {
    extern __shared__ float smf[];
    float* Qs = smf + FL_Q;
    float* Ks = smf + FL_K;
    float* Vs = smf + FL_V;
    float* Ps = smf + FL_P;

    const int t    = threadIdx.x;
    const int w    = t >> 5;
    const int lane = t & 31;
    const int g    = lane >> 2;   // 0..7
    const int kq   = lane & 3;    // 0..3
    const int nh = blockIdx.y;
    const int qt = blockIdx.x;
    const float* Qg = g_q + ((size_t)nh * LL + qt * 64) * HD;
    const float* Kg = g_k + (size_t)nh * LL * HD;
    const float* Vg = g_v + (size_t)nh * LL * HD;

    // load Q, split hi/lo interleaved
    for (int idx = t; idx < 64*16; idx += 128) {
        int r = idx >> 4, c4 = (idx & 15) << 2;
        float4 v = *reinterpret_cast<const float4*>(&Qg[r*64 + c4]);
        float2* qrow = reinterpret_cast<float2*>(&Qs[r*QKSTR]);
        float h0 = tf32r(v.x), h1 = tf32r(v.y), h2 = tf32r(v.z), h3 = tf32r(v.w);
        qrow[c4+0] = make_float2(h0, tf32r(v.x - h0));
        qrow[c4+1] = make_float2(h1, tf32r(v.y - h1));
        qrow[c4+2] = make_float2(h2, tf32r(v.z - h2));
        qrow[c4+3] = make_float2(h3, tf32r(v.w - h3));
    }

    float acc[8][4] = {};
    float miA = -1e30f, miB = -1e30f, liA = 0.0f, liB = 0.0f;

    const int rA = w*16 + g;     // this thread's even row
    const int rB = rA + 8;

    for (int kt = 0; kt < 16; kt++) {
        const float* Kt = Kg + kt * 64 * 64;
        const float* Vt = Vg + kt * 64 * 64;
        for (int idx = t; idx < 64*16; idx += 128) {
            int r = idx >> 4, c4 = (idx & 15) << 2;
            float4 v = *reinterpret_cast<const float4*>(&Kt[r*64 + c4]);
            float2* krow = reinterpret_cast<float2*>(&Ks[r*QKSTR]);
            float h0 = tf32r(v.x), h1 = tf32r(v.y), h2 = tf32r(v.z), h3 = tf32r(v.w);
            krow[c4+0] = make_float2(h0, tf32r(v.x - h0));
            krow[c4+1] = make_float2(h1, tf32r(v.y - h1));
            krow[c4+2] = make_float2(h2, tf32r(v.z - h2));
            krow[c4+3] = make_float2(h3, tf32r(v.w - h3));
            float4 vv = *reinterpret_cast<const float4*>(&Vt[r*64 + c4]);
            Vs[r*VSTR + c4+0] = tf32r(vv.x);
            Vs[r*VSTR + c4+1] = tf32r(vv.y);
            Vs[r*VSTR + c4+2] = tf32r(vv.z);
            Vs[r*VSTR + c4+3] = tf32r(vv.w);
        }
        __syncthreads();

        // ---- S = Q @ K^T (3xTF32) ----
        float sd[8][4] = {};
        #pragma unroll
        for (int kb = 0; kb < 8; kb++) {
            const float2* qr0 = reinterpret_cast<const float2*>(&Qs[rA*QKSTR]);
            const float2* qr1 = reinterpret_cast<const float2*>(&Qs[rB*QKSTR]);
            float2 a0 = qr0[kb*8+kq],   a1 = qr1[kb*8+kq];
            float2 a2 = qr0[kb*8+kq+4], a3 = qr1[kb*8+kq+4];
            uint32_t ahi[4] = {__float_as_uint(a0.x), __float_as_uint(a1.x),
                               __float_as_uint(a2.x), __float_as_uint(a3.x)};
            uint32_t alo[4] = {__float_as_uint(a0.y), __float_as_uint(a1.y),
                               __float_as_uint(a2.y), __float_as_uint(a3.y)};
            #pragma unroll
            for (int j = 0; j < 8; j++) {
                const float2* kr = reinterpret_cast<const float2*>(&Ks[(j*8+g)*QKSTR]);
                float2 b0 = kr[kb*8+kq], b1 = kr[kb*8+kq+4];
                uint32_t bhi[2] = {__float_as_uint(b0.x), __float_as_uint(b1.x)};
                uint32_t blo[2] = {__float_as_uint(b0.y), __float_as_uint(b1.y)};
                mma_tf32_16x8x8(sd[j], ahi, bhi);
                mma_tf32_16x8x8(sd[j], ahi, blo);
                mma_tf32_16x8x8(sd[j], alo, bhi);
            }
        }

        // ---- online softmax (rows rA via c0/c1, rB via c2/c3) ----
        float rmA = -1e30f, rmB = -1e30f;
        #pragma unroll
        for (int j = 0; j < 8; j++) {
            rmA = fmaxf(rmA, fmaxf(sd[j][0], sd[j][1]));
            rmB = fmaxf(rmB, fmaxf(sd[j][2], sd[j][3]));
        }
        rmA = fmaxf(rmA, __shfl_xor_sync(0xffffffffu, rmA, 1));
        rmA = fmaxf(rmA, __shfl_xor_sync(0xffffffffu, rmA, 2));
        rmB = fmaxf(rmB, __shfl_xor_sync(0xffffffffu, rmB, 1));
        rmB = fmaxf(rmB, __shfl_xor_sync(0xffffffffu, rmB, 2));
        float mA = fmaxf(miA, rmA), mB = fmaxf(miB, rmB);
        float corrA = __expf(miA - mA), corrB = __expf(miB - mB);
        float sumA = 0.0f, sumB = 0.0f;
        #pragma unroll
        for (int j = 0; j < 8; j++) {
            float p0 = __expf(sd[j][0] - mA);
            float p1 = __expf(sd[j][1] - mA);
            float p2 = __expf(sd[j][2] - mB);
            float p3 = __expf(sd[j][3] - mB);
            sumA += p0 + p1;
            sumB += p2 + p3;
            *reinterpret_cast<float2*>(&Ps[rA*PSTR + j*8 + 2*kq]) =
                make_float2(tf32r(p0), tf32r(p1));
            *reinterpret_cast<float2*>(&Ps[rB*PSTR + j*8 + 2*kq]) =
                make_float2(tf32r(p2), tf32r(p3));
            acc[j][0] *= corrA; acc[j][1] *= corrA;
            acc[j][2] *= corrB; acc[j][3] *= corrB;
        }
        sumA += __shfl_xor_sync(0xffffffffu, sumA, 1);
        sumA += __shfl_xor_sync(0xffffffffu, sumA, 2);
        sumB += __shfl_xor_sync(0xffffffffu, sumB, 1);
        sumB += __shfl_xor_sync(0xffffffffu, sumB, 2);
        liA = liA * corrA + sumA;  miA = mA;
        liB = liB * corrB + sumB;  miB = mB;
        __syncwarp();   // Ps rows are warp-private; warp-level visibility suffices

        // ---- O += P @ V (single tf32) ----
        #pragma unroll
        for (int kb = 0; kb < 8; kb++) {
            uint32_t pa[4];
            pa[0] = __float_as_uint(Ps[rA*PSTR + kb*8+kq]);
            pa[1] = __float_as_uint(Ps[rB*PSTR + kb*8+kq]);
            pa[2] = __float_as_uint(Ps[rA*PSTR + kb*8+kq+4]);
            pa[3] = __float_as_uint(Ps[rB*PSTR + kb*8+kq+4]);
            #pragma unroll
            for (int j = 0; j < 8; j++) {
                uint32_t vb[2];
                vb[0] = __float_as_uint(Vs[(kb*8+kq)*VSTR   + j*8+g]);
                vb[1] = __float_as_uint(Vs[(kb*8+kq+4)*VSTR + j*8+g]);
                mma_tf32_16x8x8(acc[j], pa, vb);
            }
        }
        __syncthreads();   // all warps done with Ks/Vs before next tile load
    }

    // ---- epilogue ----
    const int h = nh & 15;
    const int n = nh >> 4;
    const float hs = head_scale[h];
    const float sAf = hs / liA, sBf = hs / liB;
    const int lA = qt*64 + rA;
    const int lB = qt*64 + rB;
    #pragma unroll
    for (int j = 0; j < 8; j++) {
        const int col = h*HD + j*8 + 2*kq;
        *reinterpret_cast<float2*>(&g_o[(size_t)(lA*NB + n)*CC + col]) =
            make_float2(acc[j][0]*sAf, acc[j][1]*sAf);
        *reinterpret_cast<float2*>(&g_o[(size_t)(lB*NB + n)*CC + col]) =
            make_float2(acc[j][2]*sBf, acc[j][3]*sBf);
    }
}

// ============================================================
extern "C" void kernel_launch(void* const* d_in, const int* in_sizes, int n_in,
                              void* d_out, int out_size) {
    const float* x           = (const float*)d_in[0];
    const float* w_in        = (const float*)d_in[1];
    const float* b_in        = (const float*)d_in[2];
    const float* logit_scale = (const float*)d_in[3];
    const float* head_scale  = (const float*)d_in[4];
    const float* out_w       = (const float*)d_in[5];
    const float* out_b       = (const float*)d_in[6];
    float* out = (float*)d_out;

    float *qkv_p, *o_p;
    cudaGetSymbolAddress((void**)&qkv_p, g_qkv);
    cudaGetSymbolAddress((void**)&o_p, g_o);

    cudaFuncSetAttribute(flash_attn_mma,
                         cudaFuncAttributeMaxDynamicSharedMemorySize, FLASH_SMEM);

    // 1) qkv = x @ W^T + b   (tf32 mma.sync)
    gemm_tf32_mma<<<dim3(C3/128, MM/128), 256>>>(x, w_in, b_in, qkv_p, CC, C3);
    // 2) normalize + scatter
    norm_scatter_kernel<<<(3*NHH*LL)/8, 256>>>(logit_scale);
    // 3) flash attention (tf32 mma, 3xTF32 logits)
    flash_attn_mma<<<dim3(LL/64, NHH), 128, FLASH_SMEM>>>(head_scale);
    // 4) out = o @ out_w^T + out_b  (tf32 mma.sync)
    gemm_tf32_mma<<<dim3(CC/128, MM/128), 256>>>(o_p, out_w, out_b, out, CC, CC);
}

// round 5
// speedup vs baseline: 1.7811x; 1.0340x over previous
#include <cuda_runtime.h>
#include <math.h>
#include <stdint.h>

#define LL 1024
#define NB 8
#define CC 1024
#define HH 16
#define HD 64
#define MM (LL*NB)          // 8192
#define C3 (3*CC)           // 3072
#define NHH (NB*HH)         // 128
#define LOGIT_MAX 4.605170185988091f

// ---- scratch (device globals) ----
__device__ float g_qkv[(size_t)MM * C3];
__device__ float g_q[(size_t)NHH * LL * HD];
__device__ float g_k[(size_t)NHH * LL * HD];
__device__ float g_v[(size_t)NHH * LL * HD];
__device__ float g_o[(size_t)MM * CC];

__device__ __forceinline__ float tf32r(float x) {
    uint32_t u;
    asm("cvt.rna.tf32.f32 %0, %1;" : "=r"(u) : "f"(x));
    return __uint_as_float(u);
}

__device__ __forceinline__ void mma_tf32_16x8x8(float* d, const uint32_t* a, const uint32_t* b) {
    asm volatile(
        "mma.sync.aligned.m16n8k8.row.col.f32.tf32.tf32.f32 "
        "{%0,%1,%2,%3}, {%4,%5,%6,%7}, {%8,%9}, {%0,%1,%2,%3};\n"
        : "+f"(d[0]), "+f"(d[1]), "+f"(d[2]), "+f"(d[3])
        : "r"(a[0]), "r"(a[1]), "r"(a[2]), "r"(a[3]), "r"(b[0]), "r"(b[1]));
}

// ============================================================
// tf32 mma.sync GEMM (NT), fragment-order smem + double buffer.
// C[m][n] = sum_k A[m][k]*B[n][k] + bias[n]
// BM=BN=128, BK=16, 256 threads (8 warps 2x4), warp tile 64x32.
//
// Smem fragment layout (per k8 chunk c):
//  A: idx = (c*8 + mtile)*132 + (g*4+kq)*4 + e,  e = khalf*2 + half
//     (thread (g,kq) of an mtile reads its 4 a-regs as one LDS.128)
//  B: idx = (c*16 + ntile)*68 + (g*4+kq)*2 + khalf  (one LDS.64)
// Stage sizes: A 2112 floats, B 2176 floats; 2 stages each.
// ============================================================
#define ASTG 2112
#define BSTG 2176

__global__ __launch_bounds__(256, 2)
void gemm_tf32_mma(const float* __restrict__ A, const float* __restrict__ B,
                   const float* __restrict__ bias, float* __restrict__ C,
                   int K, int Ncols) {
    __shared__ float As[2*ASTG];
    __shared__ float Bs[2*BSTG];
    const int t  = threadIdx.x;
    const int m0 = blockIdx.y * 128;
    const int n0 = blockIdx.x * 128;
    const int lr = t >> 2;            // 0..63 (loader row)
    const int lq = t & 3;             // 0..3  (loader k-quad within k16)
    const int wid  = t >> 5;
    const int lane = t & 31;
    const int g  = lane >> 2;         // 0..7
    const int kq = lane & 3;          // 0..3
    const int wm4 = (wid >> 2) * 4;   // warp mtile base (0 or 4)
    const int wn8 = (wid & 3) * 4;    // warp ntile base (0,4,8,12)

    // loader-side fragment coordinates
    const int cs = lq >> 1;           // k8 chunk of this quad
    const int kh = lq & 1;            // khalf of this quad
    const int gs = lr & 7;
    const int eA = kh*2 + ((lr >> 3) & 1);
    const int stA0 = ((cs*8  + (lr >> 4)) * 132) + eA;   // + p*4*132 for rows +64
    const int stB0 = ((cs*16 + (lr >> 3)) * 68)  + kh;   // + p*8*68

    float acc[4][4][4] = {};

    const float* Ap0 = A + (size_t)(m0 + lr) * K + lq * 4;
    const float* Ap1 = Ap0 + (size_t)64 * K;
    const float* Bp0 = B + (size_t)(n0 + lr) * K + lq * 4;
    const float* Bp1 = Bp0 + (size_t)64 * K;

    float4 ra0 = *reinterpret_cast<const float4*>(Ap0);
    float4 ra1 = *reinterpret_cast<const float4*>(Ap1);
    float4 rb0 = *reinterpret_cast<const float4*>(Bp0);
    float4 rb1 = *reinterpret_cast<const float4*>(Bp1);

#define STORE_STAGE(asn, bsn)                                                   \
    {                                                                           \
        float* a0p = (asn) + stA0;                                              \
        a0p[(gs*4+0)*4] = tf32r(ra0.x); a0p[(gs*4+1)*4] = tf32r(ra0.y);         \
        a0p[(gs*4+2)*4] = tf32r(ra0.z); a0p[(gs*4+3)*4] = tf32r(ra0.w);         \
        float* a1p = (asn) + stA0 + 4*132;                                      \
        a1p[(gs*4+0)*4] = tf32r(ra1.x); a1p[(gs*4+1)*4] = tf32r(ra1.y);         \
        a1p[(gs*4+2)*4] = tf32r(ra1.z); a1p[(gs*4+3)*4] = tf32r(ra1.w);         \
        float* b0p = (bsn) + stB0;                                              \
        b0p[(gs*4+0)*2] = tf32r(rb0.x); b0p[(gs*4+1)*2] = tf32r(rb0.y);         \
        b0p[(gs*4+2)*2] = tf32r(rb0.z); b0p[(gs*4+3)*2] = tf32r(rb0.w);         \
        float* b1p = (bsn) + stB0 + 8*68;                                       \
        b1p[(gs*4+0)*2] = tf32r(rb1.x); b1p[(gs*4+1)*2] = tf32r(rb1.y);         \
        b1p[(gs*4+2)*2] = tf32r(rb1.z); b1p[(gs*4+3)*2] = tf32r(rb1.w);         \
    }

    STORE_STAGE(As, Bs);
    __syncthreads();

    int cur = 0;
    for (int k0 = 0; k0 < K; k0 += 16) {
        const bool more = (k0 + 16) < K;
        if (more) {
            ra0 = *reinterpret_cast<const float4*>(Ap0 + k0 + 16);
            ra1 = *reinterpret_cast<const float4*>(Ap1 + k0 + 16);
            rb0 = *reinterpret_cast<const float4*>(Bp0 + k0 + 16);
            rb1 = *reinterpret_cast<const float4*>(Bp1 + k0 + 16);
        }
        const float* as = As + cur * ASTG;
        const float* bs = Bs + cur * BSTG;
        #pragma unroll
        for (int c = 0; c < 2; c++) {
            uint32_t a[4][4], b[4][2];
            #pragma unroll
            for (int ti = 0; ti < 4; ti++) {
                float4 af = *reinterpret_cast<const float4*>(
                    &as[(c*8 + wm4 + ti)*132 + (g*4+kq)*4]);
                a[ti][0] = __float_as_uint(af.x);
                a[ti][1] = __float_as_uint(af.y);
                a[ti][2] = __float_as_uint(af.z);
                a[ti][3] = __float_as_uint(af.w);
            }
            #pragma unroll
            for (int j = 0; j < 4; j++) {
                float2 bf = *reinterpret_cast<const float2*>(
                    &bs[(c*16 + wn8 + j)*68 + (g*4+kq)*2]);
                b[j][0] = __float_as_uint(bf.x);
                b[j][1] = __float_as_uint(bf.y);
            }
            #pragma unroll
            for (int ti = 0; ti < 4; ti++)
                #pragma unroll
                for (int j = 0; j < 4; j++)
                    mma_tf32_16x8x8(acc[ti][j], a[ti], b[j]);
        }
        if (more) {
            float* asn = As + (cur ^ 1) * ASTG;
            float* bsn = Bs + (cur ^ 1) * BSTG;
            STORE_STAGE(asn, bsn);
        }
        __syncthreads();
        cur ^= 1;
    }
#undef STORE_STAGE

    // epilogue: acc[ti][j]: rows m0+wm4*16+ti*16+g (+8), cols n0+wn8*8+j*8+2*kq (+1)
    #pragma unroll
    for (int ti = 0; ti < 4; ti++) {
        const int r0 = m0 + wm4*16 + ti*16 + g;
        #pragma unroll
        for (int j = 0; j < 4; j++) {
            const int c0 = n0 + wn8*8 + j*8 + 2*kq;
            const float bx = bias[c0], by = bias[c0+1];
            float2 lo, hi;
            lo.x = acc[ti][j][0] + bx; lo.y = acc[ti][j][1] + by;
            hi.x = acc[ti][j][2] + bx; hi.y = acc[ti][j][3] + by;
            *reinterpret_cast<float2*>(&C[(size_t)r0 * Ncols + c0]) = lo;
            *reinterpret_cast<float2*>(&C[(size_t)(r0+8) * Ncols + c0]) = hi;
        }
    }
}

// ============================================================
// Normalize + scatter (unchanged).
// ============================================================
__global__ __launch_bounds__(256)
void norm_scatter_kernel(const float* __restrict__ logit_scale) {
    const int warp = (blockIdx.x * blockDim.x + threadIdx.x) >> 5;
    const int lane = threadIdx.x & 31;
    const int tsel = warp / (NHH * LL);
    const int rr   = warp - tsel * (NHH * LL);
    const int nh   = rr >> 10;
    const int l    = rr & 1023;
    const int n    = nh >> 4;
    const int h    = nh & 15;
    const size_t src = (size_t)(l * NB + n) * C3 + (size_t)tsel * CC + h * HD;
    float v0 = g_qkv[src + lane];
    float v1 = g_qkv[src + lane + 32];
    if (tsel < 2) {
        float s = v0*v0 + v1*v1;
        #pragma unroll
        for (int o = 16; o > 0; o >>= 1) s += __shfl_xor_sync(0xffffffffu, s, o);
        float inv = 1.0f / fmaxf(sqrtf(s), 1e-12f);
        if (tsel == 0) inv *= expf(fminf(logit_scale[h], LOGIT_MAX));
        v0 *= inv; v1 *= inv;
    }
    float* dst = (tsel == 0) ? g_q : ((tsel == 1) ? g_k : g_v);
    const size_t o = ((size_t)nh * LL + l) * HD;
    dst[o + lane]      = v0;
    dst[o + lane + 32] = v1;
}

// ============================================================
// Flash attention with tf32 mma.sync (unchanged from R4, passing).
// ============================================================
#define QKSTR 132
#define VSTR  72
#define PSTR  72
#define FL_Q 0
#define FL_K (64*QKSTR)
#define FL_V (2*64*QKSTR)
#define FL_P (2*64*QKSTR + 64*VSTR)
#define FLASH_SMEM ((2*64*QKSTR + 64*VSTR + 64*PSTR) * (int)sizeof(float))

__global__ __launch_bounds__(128, 2)
void flash_attn_mma(const float* __restrict__ head_scale) {
    extern __shared__ float smf[];
    float* Qs = smf + FL_Q;
    float* Ks = smf + FL_K;
    float* Vs = smf + FL_V;
    float* Ps = smf + FL_P;

    const int t    = threadIdx.x;
    const int w    = t >> 5;
    const int lane = t & 31;
    const int g    = lane >> 2;
    const int kq   = lane & 3;
    const int nh = blockIdx.y;
    const int qt = blockIdx.x;
    const float* Qg = g_q + ((size_t)nh * LL + qt * 64) * HD;
    const float* Kg = g_k + (size_t)nh * LL * HD;
    const float* Vg = g_v + (size_t)nh * LL * HD;

    for (int idx = t; idx < 64*16; idx += 128) {
        int r = idx >> 4, c4 = (idx & 15) << 2;
        float4 v = *reinterpret_cast<const float4*>(&Qg[r*64 + c4]);
        float2* qrow = reinterpret_cast<float2*>(&Qs[r*QKSTR]);
        float h0 = tf32r(v.x), h1 = tf32r(v.y), h2 = tf32r(v.z), h3 = tf32r(v.w);
        qrow[c4+0] = make_float2(h0, tf32r(v.x - h0));
        qrow[c4+1] = make_float2(h1, tf32r(v.y - h1));
        qrow[c4+2] = make_float2(h2, tf32r(v.z - h2));
        qrow[c4+3] = make_float2(h3, tf32r(v.w - h3));
    }

    float acc[8][4] = {};
    float miA = -1e30f, miB = -1e30f, liA = 0.0f, liB = 0.0f;

    const int rA = w*16 + g;
    const int rB = rA + 8;

    for (int kt = 0; kt < 16; kt++) {
        const float* Kt = Kg + kt * 64 * 64;
        const float* Vt = Vg + kt * 64 * 64;
        for (int idx = t; idx < 64*16; idx += 128) {
            int r = idx >> 4, c4 = (idx & 15) << 2;
            float4 v = *reinterpret_cast<const float4*>(&Kt[r*64 + c4]);
            float2* krow = reinterpret_cast<float2*>(&Ks[r*QKSTR]);
            float h0 = tf32r(v.x), h1 = tf32r(v.y), h2 = tf32r(v.z), h3 = tf32r(v.w);
            krow[c4+0] = make_float2(h0, tf32r(v.x - h0));
            krow[c4+1] = make_float2(h1, tf32r(v.y - h1));
            krow[c4+2] = make_float2(h2, tf32r(v.z - h2));
            krow[c4+3] = make_float2(h3, tf32r(v.w - h3));
            float4 vv = *reinterpret_cast<const float4*>(&Vt[r*64 + c4]);
            Vs[r*VSTR + c4+0] = tf32r(vv.x);
            Vs[r*VSTR + c4+1] = tf32r(vv.y);
            Vs[r*VSTR + c4+2] = tf32r(vv.z);
            Vs[r*VSTR + c4+3] = tf32r(vv.w);
        }
        __syncthreads();

        float sd[8][4] = {};
        #pragma unroll
        for (int kb = 0; kb < 8; kb++) {
            const float2* qr0 = reinterpret_cast<const float2*>(&Qs[rA*QKSTR]);
            const float2* qr1 = reinterpret_cast<const float2*>(&Qs[rB*QKSTR]);
            float2 a0 = qr0[kb*8+kq],   a1 = qr1[kb*8+kq];
            float2 a2 = qr0[kb*8+kq+4], a3 = qr1[kb*8+kq+4];
            uint32_t ahi[4] = {__float_as_uint(a0.x), __float_as_uint(a1.x),
                               __float_as_uint(a2.x), __float_as_uint(a3.x)};
            uint32_t alo[4] = {__float_as_uint(a0.y), __float_as_uint(a1.y),
                               __float_as_uint(a2.y), __float_as_uint(a3.y)};
            #pragma unroll
            for (int j = 0; j < 8; j++) {
                const float2* kr = reinterpret_cast<const float2*>(&Ks[(j*8+g)*QKSTR]);
                float2 b0 = kr[kb*8+kq], b1 = kr[kb*8+kq+4];
                uint32_t bhi[2] = {__float_as_uint(b0.x), __float_as_uint(b1.x)};
                uint32_t blo[2] = {__float_as_uint(b0.y), __float_as_uint(b1.y)};
                mma_tf32_16x8x8(sd[j], ahi, bhi);
                mma_tf32_16x8x8(sd[j], ahi, blo);
                mma_tf32_16x8x8(sd[j], alo, bhi);
            }
        }

        float rmA = -1e30f, rmB = -1e30f;
        #pragma unroll
        for (int j = 0; j < 8; j++) {
            rmA = fmaxf(rmA, fmaxf(sd[j][0], sd[j][1]));
            rmB = fmaxf(rmB, fmaxf(sd[j][2], sd[j][3]));
        }
        rmA = fmaxf(rmA, __shfl_xor_sync(0xffffffffu, rmA, 1));
        rmA = fmaxf(rmA, __shfl_xor_sync(0xffffffffu, rmA, 2));
        rmB = fmaxf(rmB, __shfl_xor_sync(0xffffffffu, rmB, 1));
        rmB = fmaxf(rmB, __shfl_xor_sync(0xffffffffu, rmB, 2));
        float mA = fmaxf(miA, rmA), mB = fmaxf(miB, rmB);
        float corrA = __expf(miA - mA), corrB = __expf(miB - mB);
        float sumA = 0.0f, sumB = 0.0f;
        #pragma unroll
        for (int j = 0; j < 8; j++) {
            float p0 = __expf(sd[j][0] - mA);
            float p1 = __expf(sd[j][1] - mA);
            float p2 = __expf(sd[j][2] - mB);
            float p3 = __expf(sd[j][3] - mB);
            sumA += p0 + p1;
            sumB += p2 + p3;
            *reinterpret_cast<float2*>(&Ps[rA*PSTR + j*8 + 2*kq]) =
                make_float2(tf32r(p0), tf32r(p1));
            *reinterpret_cast<float2*>(&Ps[rB*PSTR + j*8 + 2*kq]) =
                make_float2(tf32r(p2), tf32r(p3));
            acc[j][0] *= corrA; acc[j][1] *= corrA;
            acc[j][2] *= corrB; acc[j][3] *= corrB;
        }
        sumA += __shfl_xor_sync(0xffffffffu, sumA, 1);
        sumA += __shfl_xor_sync(0xffffffffu, sumA, 2);
        sumB += __shfl_xor_sync(0xffffffffu, sumB, 1);
        sumB += __shfl_xor_sync(0xffffffffu, sumB, 2);
        liA = liA * corrA + sumA;  miA = mA;
        liB = liB * corrB + sumB;  miB = mB;
        __syncwarp();

        #pragma unroll
        for (int kb = 0; kb < 8; kb++) {
            uint32_t pa[4];
            pa[0] = __float_as_uint(Ps[rA*PSTR + kb*8+kq]);
            pa[1] = __float_as_uint(Ps[rB*PSTR + kb*8+kq]);
            pa[2] = __float_as_uint(Ps[rA*PSTR + kb*8+kq+4]);
            pa[3] = __float_as_uint(Ps[rB*PSTR + kb*8+kq+4]);
            #pragma unroll
            for (int j = 0; j < 8; j++) {
                uint32_t vb[2];
                vb[0] = __float_as_uint(Vs[(kb*8+kq)*VSTR   + j*8+g]);
                vb[1] = __float_as_uint(Vs[(kb*8+kq+4)*VSTR + j*8+g]);
                mma_tf32_16x8x8(acc[j], pa, vb);
            }
        }
        __syncthreads();
    }

    const int h = nh & 15;
    const int n = nh >> 4;
    const float hs = head_scale[h];
    const float sAf = hs / liA, sBf = hs / liB;
    const int lA = qt*64 + rA;
    const int lB = qt*64 + rB;
    #pragma unroll
    for (int j = 0; j < 8; j++) {
        const int col = h*HD + j*8 + 2*kq;
        *reinterpret_cast<float2*>(&g_o[(size_t)(lA*NB + n)*CC + col]) =
            make_float2(acc[j][0]*sAf, acc[j][1]*sAf);
        *reinterpret_cast<float2*>(&g_o[(size_t)(lB*NB + n)*CC + col]) =
            make_float2(acc[j][2]*sBf, acc[j][3]*sBf);
    }
}

// ============================================================
extern "C" void kernel_launch(void* const* d_in, const int* in_sizes, int n_in,
                              void* d_out, int out_size) {
    const float* x           = (const float*)d_in[0];
    const float* w_in        = (const float*)d_in[1];
    const float* b_in        = (const float*)d_in[2];
    const float* logit_scale = (const float*)d_in[3];
    const float* head_scale  = (const float*)d_in[4];
    const float* out_w       = (const float*)d_in[5];
    const float* out_b       = (const float*)d_in[6];
    float* out = (float*)d_out;

    float *qkv_p, *o_p;
    cudaGetSymbolAddress((void**)&qkv_p, g_qkv);
    cudaGetSymbolAddress((void**)&o_p, g_o);

    cudaFuncSetAttribute(flash_attn_mma,
                         cudaFuncAttributeMaxDynamicSharedMemorySize, FLASH_SMEM);

    // 1) qkv = x @ W^T + b   (tf32 mma.sync, double-buffered)
    gemm_tf32_mma<<<dim3(C3/128, MM/128), 256>>>(x, w_in, b_in, qkv_p, CC, C3);
    // 2) normalize + scatter
    norm_scatter_kernel<<<(3*NHH*LL)/8, 256>>>(logit_scale);
    // 3) flash attention (tf32 mma, 3xTF32 logits)
    flash_attn_mma<<<dim3(LL/64, NHH), 128, FLASH_SMEM>>>(head_scale);
    // 4) out = o @ out_w^T + out_b
    gemm_tf32_mma<<<dim3(CC/128, MM/128), 256>>>(o_p, out_w, out_b, out, CC, CC);
}

// round 6
// speedup vs baseline: 2.3827x; 1.3378x over previous
#include <cuda_runtime.h>
#include <math.h>
#include <stdint.h>

#define LL 1024
#define NB 8
#define CC 1024
#define HH 16
#define HD 64
#define MM (LL*NB)          // 8192
#define C3 (3*CC)           // 3072
#define NHH (NB*HH)         // 128
#define LOGIT_MAX 4.605170185988091f
#define KIT 64              // K=1024 -> 64 k16 stages

// ---- scratch (device globals) ----
__device__ float g_qkv[(size_t)MM * C3];
__device__ float g_q[(size_t)NHH * LL * HD];
__device__ float g_k[(size_t)NHH * LL * HD];
__device__ float g_v[(size_t)NHH * LL * HD];
__device__ float g_o[(size_t)MM * CC];
__device__ float g_xp[(size_t)MM * CC];    // packed x
__device__ float g_op[(size_t)MM * CC];    // packed attn-out
__device__ float g_w1p[(size_t)C3 * CC];   // packed in_proj_weight
__device__ float g_w2p[(size_t)CC * CC];   // packed out_w

__device__ __forceinline__ float tf32r(float x) {
    uint32_t u;
    asm("cvt.rna.tf32.f32 %0, %1;" : "=r"(u) : "f"(x));
    return __uint_as_float(u);
}
__device__ __forceinline__ uint32_t smem_u32(const void* p) {
    uint32_t a;
    asm("{ .reg .u64 t; cvta.to.shared.u64 t, %1; cvt.u32.u64 %0, t; }" : "=r"(a) : "l"(p));
    return a;
}
__device__ __forceinline__ void cp16(uint32_t dst, const void* src) {
    asm volatile("cp.async.cg.shared.global [%0], [%1], 16;" :: "r"(dst), "l"(src));
}
__device__ __forceinline__ void cp_commit() {
    asm volatile("cp.async.commit_group;");
}
__device__ __forceinline__ void cp_wait2() {
    asm volatile("cp.async.wait_group 2;");
}
__device__ __forceinline__ void mma_tf32_16x8x8(float* d, const uint32_t* a, const uint32_t* b) {
    asm volatile(
        "mma.sync.aligned.m16n8k8.row.col.f32.tf32.tf32.f32 "
        "{%0,%1,%2,%3}, {%4,%5,%6,%7}, {%8,%9}, {%0,%1,%2,%3};\n"
        : "+f"(d[0]), "+f"(d[1]), "+f"(d[2]), "+f"(d[3])
        : "r"(a[0]), "r"(a[1]), "r"(a[2]), "r"(a[3]), "r"(b[0]), "r"(b[1]));
}

// ============================================================
// Pack A [M x 1024] row-major -> fragment-order tf32 stages.
// Stage (mb, kb) = 2048 floats. Within: float4 at
// (c*8 + mt)*128 + lane*4 = {A[r0][k0], A[r0+8][k0], A[r0][k0+4], A[r0+8][k0+4]}
// r0 = mb*128+mt*16+g, k0 = kb*16+c*8+kq (g=lane>>2, kq=lane&3).
// One thread per output float4; grid = M blocks x 256.
// ============================================================
__global__ __launch_bounds__(256)
void pack_a(const float* __restrict__ src, float* __restrict__ dst) {
    const size_t d = (size_t)blockIdx.x * 256 + threadIdx.x;
    const int fi   = (int)(d & 511);          // float4 within stage
    const size_t sid = d >> 9;                // stage id = mb*KIT + kb
    const int mb = (int)(sid >> 6);
    const int kb = (int)(sid & 63);
    const int c  = fi >> 8;
    const int mt = (fi >> 5) & 7;
    const int lane = fi & 31;
    const int g  = lane >> 2;
    const int kq = lane & 3;
    const int r0 = mb*128 + mt*16 + g;
    const int k0 = kb*16 + c*8 + kq;
    float4 o;
    o.x = tf32r(src[(size_t)r0      * 1024 + k0]);
    o.y = tf32r(src[(size_t)(r0+8)  * 1024 + k0]);
    o.z = tf32r(src[(size_t)r0      * 1024 + k0 + 4]);
    o.w = tf32r(src[(size_t)(r0+8)  * 1024 + k0 + 4]);
    reinterpret_cast<float4*>(dst)[d] = o;
}

// ============================================================
// Pack B [N x 1024] row-major -> fragment-order tf32 stages.
// Stage (nb, kb) = 2048 floats. float2 at (c*16 + nt)*64 + lane*2 =
// {B[col][k0], B[col][k0+4]}, col = nb*128+nt*8+g, k0 = kb*16+c*8+kq.
// One thread per float2; grid = N*2 blocks x 256.
// ============================================================
__global__ __launch_bounds__(256)
void pack_b(const float* __restrict__ src, float* __restrict__ dst) {
    const size_t d = (size_t)blockIdx.x * 256 + threadIdx.x;
    const int fi   = (int)(d & 1023);
    const size_t sid = d >> 10;
    const int nb = (int)(sid >> 6);
    const int kb = (int)(sid & 63);
    const int c  = fi >> 9;
    const int nt = (fi >> 5) & 15;
    const int lane = fi & 31;
    const int g  = lane >> 2;
    const int kq = lane & 3;
    const int col = nb*128 + nt*8 + g;
    const int k0  = kb*16 + c*8 + kq;
    float2 o;
    o.x = tf32r(src[(size_t)col * 1024 + k0]);
    o.y = tf32r(src[(size_t)col * 1024 + k0 + 4]);
    reinterpret_cast<float2*>(dst)[d] = o;
}

// ============================================================
// tf32 mma.sync GEMM on packed operands, 4-stage cp.async pipeline.
// C[m][n] = sum_k A[m][k]*B[n][k] + bias[n]
// BM=BN=128, BK=16, 256 threads (8 warps 2x4), warp tile 64x32.
// Stage = A 2048 + B 2048 floats (16KB); 4 stages = 64KB dynamic smem.
// ============================================================
#define GEMM_SMEM (4*4096*4)

__global__ __launch_bounds__(256, 2)
void gemm_tf32_pk(const float* __restrict__ Ap, const float* __restrict__ Bp,
                  const float* __restrict__ bias, float* __restrict__ C,
                  int Ncols) {
    extern __shared__ float sm[];
    const uint32_t smb = smem_u32(sm);
    const int t  = threadIdx.x;
    const int wid  = t >> 5;
    const int lane = t & 31;
    const int g  = lane >> 2;
    const int kq = lane & 3;
    const int wm4 = (wid >> 2) * 4;   // warp mtile base (0 or 4)
    const int wn8 = (wid & 3) * 4;    // warp ntile base (0,4,8,12)
    const int m0 = blockIdx.y * 128;
    const int n0 = blockIdx.x * 128;

    const float* Ab = Ap + (size_t)blockIdx.y * KIT * 2048;
    const float* Bb = Bp + (size_t)blockIdx.x * KIT * 2048;

    float acc[4][4][4] = {};

    // issue stage j into slot j&3
    #define ISSUE(j)                                                        \
    {                                                                       \
        const uint32_t sb = smb + ((j) & 3) * 16384;                        \
        const float* ag = Ab + (size_t)(j) * 2048;                          \
        const float* bg = Bb + (size_t)(j) * 2048;                          \
        cp16(sb +            t*16, ag + t*4);                               \
        cp16(sb +  4096    + t*16, ag + 1024 + t*4);                        \
        cp16(sb +  8192    + t*16, bg + t*4);                               \
        cp16(sb + 12288    + t*16, bg + 1024 + t*4);                        \
    }

    ISSUE(0); cp_commit();
    ISSUE(1); cp_commit();
    ISSUE(2); cp_commit();

    for (int i = 0; i < KIT; i++) {
        cp_wait2();
        __syncthreads();
        const float* as = sm + (i & 3) * 4096;
        const float* bs = as + 2048;
        #pragma unroll
        for (int c = 0; c < 2; c++) {
            uint32_t a[4][4], b[4][2];
            #pragma unroll
            for (int ti = 0; ti < 4; ti++) {
                float4 af = *reinterpret_cast<const float4*>(
                    &as[(c*8 + wm4 + ti)*128 + lane*4]);
                a[ti][0] = __float_as_uint(af.x);
                a[ti][1] = __float_as_uint(af.y);
                a[ti][2] = __float_as_uint(af.z);
                a[ti][3] = __float_as_uint(af.w);
            }
            #pragma unroll
            for (int j = 0; j < 4; j++) {
                float2 bf = *reinterpret_cast<const float2*>(
                    &bs[(c*16 + wn8 + j)*64 + lane*2]);
                b[j][0] = __float_as_uint(bf.x);
                b[j][1] = __float_as_uint(bf.y);
            }
            #pragma unroll
            for (int ti = 0; ti < 4; ti++)
                #pragma unroll
                for (int j = 0; j < 4; j++)
                    mma_tf32_16x8x8(acc[ti][j], a[ti], b[j]);
        }
        const int jn = i + 3;
        if (jn < KIT) ISSUE(jn);
        cp_commit();   // commit every iter (possibly empty) to keep group count aligned
    }
    #undef ISSUE

    // epilogue: acc[ti][j]: rows m0+wm4*16+ti*16+g (+8), cols n0+wn8*8+j*8+2*kq (+1)
    #pragma unroll
    for (int ti = 0; ti < 4; ti++) {
        const int r0 = m0 + wm4*16 + ti*16 + g;
        #pragma unroll
        for (int j = 0; j < 4; j++) {
            const int c0 = n0 + wn8*8 + j*8 + 2*kq;
            const float bx = bias[c0], by = bias[c0+1];
            float2 lo, hi;
            lo.x = acc[ti][j][0] + bx; lo.y = acc[ti][j][1] + by;
            hi.x = acc[ti][j][2] + bx; hi.y = acc[ti][j][3] + by;
            *reinterpret_cast<float2*>(&C[(size_t)r0 * Ncols + c0]) = lo;
            *reinterpret_cast<float2*>(&C[(size_t)(r0+8) * Ncols + c0]) = hi;
        }
    }
}

// ============================================================
// Normalize + scatter (unchanged).
// ============================================================
__global__ __launch_bounds__(256)
void norm_scatter_kernel(const float* __restrict__ logit_scale) {
    const int warp = (blockIdx.x * blockDim.x + threadIdx.x) >> 5;
    const int lane = threadIdx.x & 31;
    const int tsel = warp / (NHH * LL);
    const int rr   = warp - tsel * (NHH * LL);
    const int nh   = rr >> 10;
    const int l    = rr & 1023;
    const int n    = nh >> 4;
    const int h    = nh & 15;
    const size_t src = (size_t)(l * NB + n) * C3 + (size_t)tsel * CC + h * HD;
    float v0 = g_qkv[src + lane];
    float v1 = g_qkv[src + lane + 32];
    if (tsel < 2) {
        float s = v0*v0 + v1*v1;
        #pragma unroll
        for (int o = 16; o > 0; o >>= 1) s += __shfl_xor_sync(0xffffffffu, s, o);
        float inv = 1.0f / fmaxf(sqrtf(s), 1e-12f);
        if (tsel == 0) inv *= expf(fminf(logit_scale[h], LOGIT_MAX));
        v0 *= inv; v1 *= inv;
    }
    float* dst = (tsel == 0) ? g_q : ((tsel == 1) ? g_k : g_v);
    const size_t o = ((size_t)nh * LL + l) * HD;
    dst[o + lane]      = v0;
    dst[o + lane + 32] = v1;
}

// ============================================================
// Flash attention with tf32 mma.sync (unchanged, passing).
// ============================================================
#define QKSTR 132
#define VSTR  72
#define PSTR  72
#define FL_Q 0
#define FL_K (64*QKSTR)
#define FL_V (2*64*QKSTR)
#define FL_P (2*64*QKSTR + 64*VSTR)
#define FLASH_SMEM ((2*64*QKSTR + 64*VSTR + 64*PSTR) * (int)sizeof(float))

__global__ __launch_bounds__(128, 2)
void flash_attn_mma(const float* __restrict__ head_scale) {
    extern __shared__ float smf[];
    float* Qs = smf + FL_Q;
    float* Ks = smf + FL_K;
    float* Vs = smf + FL_V;
    float* Ps = smf + FL_P;

    const int t    = threadIdx.x;
    const int w    = t >> 5;
    const int lane = t & 31;
    const int g    = lane >> 2;
    const int kq   = lane & 3;
    const int nh = blockIdx.y;
    const int qt = blockIdx.x;
    const float* Qg = g_q + ((size_t)nh * LL + qt * 64) * HD;
    const float* Kg = g_k + (size_t)nh * LL * HD;
    const float* Vg = g_v + (size_t)nh * LL * HD;

    for (int idx = t; idx < 64*16; idx += 128) {
        int r = idx >> 4, c4 = (idx & 15) << 2;
        float4 v = *reinterpret_cast<const float4*>(&Qg[r*64 + c4]);
        float2* qrow = reinterpret_cast<float2*>(&Qs[r*QKSTR]);
        float h0 = tf32r(v.x), h1 = tf32r(v.y), h2 = tf32r(v.z), h3 = tf32r(v.w);
        qrow[c4+0] = make_float2(h0, tf32r(v.x - h0));
        qrow[c4+1] = make_float2(h1, tf32r(v.y - h1));
        qrow[c4+2] = make_float2(h2, tf32r(v.z - h2));
        qrow[c4+3] = make_float2(h3, tf32r(v.w - h3));
    }

    float acc[8][4] = {};
    float miA = -1e30f, miB = -1e30f, liA = 0.0f, liB = 0.0f;

    const int rA = w*16 + g;
    const int rB = rA + 8;

    for (int kt = 0; kt < 16; kt++) {
        const float* Kt = Kg + kt * 64 * 64;
        const float* Vt = Vg + kt * 64 * 64;
        for (int idx = t; idx < 64*16; idx += 128) {
            int r = idx >> 4, c4 = (idx & 15) << 2;
            float4 v = *reinterpret_cast<const float4*>(&Kt[r*64 + c4]);
            float2* krow = reinterpret_cast<float2*>(&Ks[r*QKSTR]);
            float h0 = tf32r(v.x), h1 = tf32r(v.y), h2 = tf32r(v.z), h3 = tf32r(v.w);
            krow[c4+0] = make_float2(h0, tf32r(v.x - h0));
            krow[c4+1] = make_float2(h1, tf32r(v.y - h1));
            krow[c4+2] = make_float2(h2, tf32r(v.z - h2));
            krow[c4+3] = make_float2(h3, tf32r(v.w - h3));
            float4 vv = *reinterpret_cast<const float4*>(&Vt[r*64 + c4]);
            Vs[r*VSTR + c4+0] = tf32r(vv.x);
            Vs[r*VSTR + c4+1] = tf32r(vv.y);
            Vs[r*VSTR + c4+2] = tf32r(vv.z);
            Vs[r*VSTR + c4+3] = tf32r(vv.w);
        }
        __syncthreads();

        float sd[8][4] = {};
        #pragma unroll
        for (int kb = 0; kb < 8; kb++) {
            const float2* qr0 = reinterpret_cast<const float2*>(&Qs[rA*QKSTR]);
            const float2* qr1 = reinterpret_cast<const float2*>(&Qs[rB*QKSTR]);
            float2 a0 = qr0[kb*8+kq],   a1 = qr1[kb*8+kq];
            float2 a2 = qr0[kb*8+kq+4], a3 = qr1[kb*8+kq+4];
            uint32_t ahi[4] = {__float_as_uint(a0.x), __float_as_uint(a1.x),
                               __float_as_uint(a2.x), __float_as_uint(a3.x)};
            uint32_t alo[4] = {__float_as_uint(a0.y), __float_as_uint(a1.y),
                               __float_as_uint(a2.y), __float_as_uint(a3.y)};
            #pragma unroll
            for (int j = 0; j < 8; j++) {
                const float2* kr = reinterpret_cast<const float2*>(&Ks[(j*8+g)*QKSTR]);
                float2 b0 = kr[kb*8+kq], b1 = kr[kb*8+kq+4];
                uint32_t bhi[2] = {__float_as_uint(b0.x), __float_as_uint(b1.x)};
                uint32_t blo[2] = {__float_as_uint(b0.y), __float_as_uint(b1.y)};
                mma_tf32_16x8x8(sd[j], ahi, bhi);
                mma_tf32_16x8x8(sd[j], ahi, blo);
                mma_tf32_16x8x8(sd[j], alo, bhi);
            }
        }

        float rmA = -1e30f, rmB = -1e30f;
        #pragma unroll
        for (int j = 0; j < 8; j++) {
            rmA = fmaxf(rmA, fmaxf(sd[j][0], sd[j][1]));
            rmB = fmaxf(rmB, fmaxf(sd[j][2], sd[j][3]));
        }
        rmA = fmaxf(rmA, __shfl_xor_sync(0xffffffffu, rmA, 1));
        rmA = fmaxf(rmA, __shfl_xor_sync(0xffffffffu, rmA, 2));
        rmB = fmaxf(rmB, __shfl_xor_sync(0xffffffffu, rmB, 1));
        rmB = fmaxf(rmB, __shfl_xor_sync(0xffffffffu, rmB, 2));
        float mA = fmaxf(miA, rmA), mB = fmaxf(miB, rmB);
        float corrA = __expf(miA - mA), corrB = __expf(miB - mB);
        float sumA = 0.0f, sumB = 0.0f;
        #pragma unroll
        for (int j = 0; j < 8; j++) {
            float p0 = __expf(sd[j][0] - mA);
            float p1 = __expf(sd[j][1] - mA);
            float p2 = __expf(sd[j][2] - mB);
            float p3 = __expf(sd[j][3] - mB);
            sumA += p0 + p1;
            sumB += p2 + p3;
            *reinterpret_cast<float2*>(&Ps[rA*PSTR + j*8 + 2*kq]) =
                make_float2(tf32r(p0), tf32r(p1));
            *reinterpret_cast<float2*>(&Ps[rB*PSTR + j*8 + 2*kq]) =
                make_float2(tf32r(p2), tf32r(p3));
            acc[j][0] *= corrA; acc[j][1] *= corrA;
            acc[j][2] *= corrB; acc[j][3] *= corrB;
        }
        sumA += __shfl_xor_sync(0xffffffffu, sumA, 1);
        sumA += __shfl_xor_sync(0xffffffffu, sumA, 2);
        sumB += __shfl_xor_sync(0xffffffffu, sumB, 1);
        sumB += __shfl_xor_sync(0xffffffffu, sumB, 2);
        liA = liA * corrA + sumA;  miA = mA;
        liB = liB * corrB + sumB;  miB = mB;
        __syncwarp();

        #pragma unroll
        for (int kb = 0; kb < 8; kb++) {
            uint32_t pa[4];
            pa[0] = __float_as_uint(Ps[rA*PSTR + kb*8+kq]);
            pa[1] = __float_as_uint(Ps[rB*PSTR + kb*8+kq]);
            pa[2] = __float_as_uint(Ps[rA*PSTR + kb*8+kq+4]);
            pa[3] = __float_as_uint(Ps[rB*PSTR + kb*8+kq+4]);
            #pragma unroll
            for (int j = 0; j < 8; j++) {
                uint32_t vb[2];
                vb[0] = __float_as_uint(Vs[(kb*8+kq)*VSTR   + j*8+g]);
                vb[1] = __float_as_uint(Vs[(kb*8+kq+4)*VSTR + j*8+g]);
                mma_tf32_16x8x8(acc[j], pa, vb);
            }
        }
        __syncthreads();
    }

    const int h = nh & 15;
    const int n = nh >> 4;
    const float hs = head_scale[h];
    const float sAf = hs / liA, sBf = hs / liB;
    const int lA = qt*64 + rA;
    const int lB = qt*64 + rB;
    #pragma unroll
    for (int j = 0; j < 8; j++) {
        const int col = h*HD + j*8 + 2*kq;
        *reinterpret_cast<float2*>(&g_o[(size_t)(lA*NB + n)*CC + col]) =
            make_float2(acc[j][0]*sAf, acc[j][1]*sAf);
        *reinterpret_cast<float2*>(&g_o[(size_t)(lB*NB + n)*CC + col]) =
            make_float2(acc[j][2]*sBf, acc[j][3]*sBf);
    }
}

// ============================================================
extern "C" void kernel_launch(void* const* d_in, const int* in_sizes, int n_in,
                              void* d_out, int out_size) {
    const float* x           = (const float*)d_in[0];
    const float* w_in        = (const float*)d_in[1];
    const float* b_in        = (const float*)d_in[2];
    const float* logit_scale = (const float*)d_in[3];
    const float* head_scale  = (const float*)d_in[4];
    const float* out_w       = (const float*)d_in[5];
    const float* out_b       = (const float*)d_in[6];
    float* out = (float*)d_out;

    float *qkv_p, *o_p, *xp_p, *op_p, *w1p_p, *w2p_p;
    cudaGetSymbolAddress((void**)&qkv_p, g_qkv);
    cudaGetSymbolAddress((void**)&o_p,   g_o);
    cudaGetSymbolAddress((void**)&xp_p,  g_xp);
    cudaGetSymbolAddress((void**)&op_p,  g_op);
    cudaGetSymbolAddress((void**)&w1p_p, g_w1p);
    cudaGetSymbolAddress((void**)&w2p_p, g_w2p);

    cudaFuncSetAttribute(flash_attn_mma,
                         cudaFuncAttributeMaxDynamicSharedMemorySize, FLASH_SMEM);
    cudaFuncSetAttribute(gemm_tf32_pk,
                         cudaFuncAttributeMaxDynamicSharedMemorySize, GEMM_SMEM);

    // pack operands (tf32-rounded, fragment order)
    pack_a<<<MM, 256>>>(x, xp_p);
    pack_b<<<C3*2, 256>>>(w_in, w1p_p);
    pack_b<<<CC*2, 256>>>(out_w, w2p_p);

    // 1) qkv = x @ W^T + b
    gemm_tf32_pk<<<dim3(C3/128, MM/128), 256, GEMM_SMEM>>>(xp_p, w1p_p, b_in, qkv_p, C3);
    // 2) normalize + scatter
    norm_scatter_kernel<<<(3*NHH*LL)/8, 256>>>(logit_scale);
    // 3) flash attention
    flash_attn_mma<<<dim3(LL/64, NHH), 128, FLASH_SMEM>>>(head_scale);
    // 4) out = o @ out_w^T + out_b
    pack_a<<<MM, 256>>>(o_p, op_p);
    gemm_tf32_pk<<<dim3(CC/128, MM/128), 256, GEMM_SMEM>>>(op_p, w2p_p, out_b, out, CC);
}

// round 7
// speedup vs baseline: 2.7391x; 1.1496x over previous
#include <cuda_runtime.h>
#include <math.h>
#include <stdint.h>

#define LL 1024
#define NB 8
#define CC 1024
#define HH 16
#define HD 64
#define MM (LL*NB)          // 8192
#define C3 (3*CC)           // 3072
#define NHH (NB*HH)         // 128
#define LOGIT_MAX 4.605170185988091f
#define KIT 64              // K=1024 -> 64 k16 stages

// ---- scratch (device globals) ----
__device__ float g_qkv[(size_t)MM * C3];
__device__ float g_q[(size_t)NHH * LL * 128];  // hi/lo interleaved (64 MB)
__device__ float g_k[(size_t)NHH * LL * 128];  // hi/lo interleaved (64 MB)
__device__ float g_v[(size_t)NHH * LL * HD];   // tf32-rounded
__device__ float g_o[(size_t)MM * CC];
__device__ float g_xp[(size_t)MM * CC];    // packed x
__device__ float g_op[(size_t)MM * CC];    // packed attn-out
__device__ float g_w1p[(size_t)C3 * CC];   // packed in_proj_weight
__device__ float g_w2p[(size_t)CC * CC];   // packed out_w

__device__ __forceinline__ float tf32r(float x) {
    uint32_t u;
    asm("cvt.rna.tf32.f32 %0, %1;" : "=r"(u) : "f"(x));
    return __uint_as_float(u);
}
__device__ __forceinline__ uint32_t smem_u32(const void* p) {
    uint32_t a;
    asm("{ .reg .u64 t; cvta.to.shared.u64 t, %1; cvt.u32.u64 %0, t; }" : "=r"(a) : "l"(p));
    return a;
}
__device__ __forceinline__ void cp16(uint32_t dst, const void* src) {
    asm volatile("cp.async.cg.shared.global [%0], [%1], 16;" :: "r"(dst), "l"(src));
}
__device__ __forceinline__ void cp_commit() {
    asm volatile("cp.async.commit_group;");
}
__device__ __forceinline__ void cp_wait2() {
    asm volatile("cp.async.wait_group 2;");
}
__device__ __forceinline__ void cp_wait0() {
    asm volatile("cp.async.wait_group 0;");
}
__device__ __forceinline__ void mma_tf32_16x8x8(float* d, const uint32_t* a, const uint32_t* b) {
    asm volatile(
        "mma.sync.aligned.m16n8k8.row.col.f32.tf32.tf32.f32 "
        "{%0,%1,%2,%3}, {%4,%5,%6,%7}, {%8,%9}, {%0,%1,%2,%3};\n"
        : "+f"(d[0]), "+f"(d[1]), "+f"(d[2]), "+f"(d[3])
        : "r"(a[0]), "r"(a[1]), "r"(a[2]), "r"(a[3]), "r"(b[0]), "r"(b[1]));
}

// ============================================================
// Pack A [M x 1024] row-major -> fragment-order tf32 stages (unchanged).
// ============================================================
__global__ __launch_bounds__(256)
void pack_a(const float* __restrict__ src, float* __restrict__ dst) {
    const size_t d = (size_t)blockIdx.x * 256 + threadIdx.x;
    const int fi   = (int)(d & 511);
    const size_t sid = d >> 9;
    const int mb = (int)(sid >> 6);
    const int kb = (int)(sid & 63);
    const int c  = fi >> 8;
    const int mt = (fi >> 5) & 7;
    const int lane = fi & 31;
    const int g  = lane >> 2;
    const int kq = lane & 3;
    const int r0 = mb*128 + mt*16 + g;
    const int k0 = kb*16 + c*8 + kq;
    float4 o;
    o.x = tf32r(src[(size_t)r0      * 1024 + k0]);
    o.y = tf32r(src[(size_t)(r0+8)  * 1024 + k0]);
    o.z = tf32r(src[(size_t)r0      * 1024 + k0 + 4]);
    o.w = tf32r(src[(size_t)(r0+8)  * 1024 + k0 + 4]);
    reinterpret_cast<float4*>(dst)[d] = o;
}

// ============================================================
// Pack B [N x 1024] row-major -> fragment-order tf32 stages (unchanged).
// ============================================================
__global__ __launch_bounds__(256)
void pack_b(const float* __restrict__ src, float* __restrict__ dst) {
    const size_t d = (size_t)blockIdx.x * 256 + threadIdx.x;
    const int fi   = (int)(d & 1023);
    const size_t sid = d >> 10;
    const int nb = (int)(sid >> 6);
    const int kb = (int)(sid & 63);
    const int c  = fi >> 9;
    const int nt = (fi >> 5) & 15;
    const int lane = fi & 31;
    const int g  = lane >> 2;
    const int kq = lane & 3;
    const int col = nb*128 + nt*8 + g;
    const int k0  = kb*16 + c*8 + kq;
    float2 o;
    o.x = tf32r(src[(size_t)col * 1024 + k0]);
    o.y = tf32r(src[(size_t)col * 1024 + k0 + 4]);
    reinterpret_cast<float2*>(dst)[d] = o;
}

// ============================================================
// tf32 mma.sync GEMM on packed operands (unchanged from R6, passing).
// ============================================================
#define GEMM_SMEM (4*4096*4)

__global__ __launch_bounds__(256, 2)
void gemm_tf32_pk(const float* __restrict__ Ap, const float* __restrict__ Bp,
                  const float* __restrict__ bias, float* __restrict__ C,
                  int Ncols) {
    extern __shared__ float sm[];
    const uint32_t smb = smem_u32(sm);
    const int t  = threadIdx.x;
    const int wid  = t >> 5;
    const int lane = t & 31;
    const int g  = lane >> 2;
    const int kq = lane & 3;
    const int wm4 = (wid >> 2) * 4;
    const int wn8 = (wid & 3) * 4;
    const int m0 = blockIdx.y * 128;
    const int n0 = blockIdx.x * 128;

    const float* Ab = Ap + (size_t)blockIdx.y * KIT * 2048;
    const float* Bb = Bp + (size_t)blockIdx.x * KIT * 2048;

    float acc[4][4][4] = {};

    #define ISSUE(j)                                                        \
    {                                                                       \
        const uint32_t sb = smb + ((j) & 3) * 16384;                        \
        const float* ag = Ab + (size_t)(j) * 2048;                          \
        const float* bg = Bb + (size_t)(j) * 2048;                          \
        cp16(sb +            t*16, ag + t*4);                               \
        cp16(sb +  4096    + t*16, ag + 1024 + t*4);                        \
        cp16(sb +  8192    + t*16, bg + t*4);                               \
        cp16(sb + 12288    + t*16, bg + 1024 + t*4);                        \
    }

    ISSUE(0); cp_commit();
    ISSUE(1); cp_commit();
    ISSUE(2); cp_commit();

    for (int i = 0; i < KIT; i++) {
        cp_wait2();
        __syncthreads();
        const float* as = sm + (i & 3) * 4096;
        const float* bs = as + 2048;
        #pragma unroll
        for (int c = 0; c < 2; c++) {
            uint32_t a[4][4], b[4][2];
            #pragma unroll
            for (int ti = 0; ti < 4; ti++) {
                float4 af = *reinterpret_cast<const float4*>(
                    &as[(c*8 + wm4 + ti)*128 + lane*4]);
                a[ti][0] = __float_as_uint(af.x);
                a[ti][1] = __float_as_uint(af.y);
                a[ti][2] = __float_as_uint(af.z);
                a[ti][3] = __float_as_uint(af.w);
            }
            #pragma unroll
            for (int j = 0; j < 4; j++) {
                float2 bf = *reinterpret_cast<const float2*>(
                    &bs[(c*16 + wn8 + j)*64 + lane*2]);
                b[j][0] = __float_as_uint(bf.x);
                b[j][1] = __float_as_uint(bf.y);
            }
            #pragma unroll
            for (int ti = 0; ti < 4; ti++)
                #pragma unroll
                for (int j = 0; j < 4; j++)
                    mma_tf32_16x8x8(acc[ti][j], a[ti], b[j]);
        }
        const int jn = i + 3;
        if (jn < KIT) ISSUE(jn);
        cp_commit();
    }
    #undef ISSUE

    #pragma unroll
    for (int ti = 0; ti < 4; ti++) {
        const int r0 = m0 + wm4*16 + ti*16 + g;
        #pragma unroll
        for (int j = 0; j < 4; j++) {
            const int c0 = n0 + wn8*8 + j*8 + 2*kq;
            const float bx = bias[c0], by = bias[c0+1];
            float2 lo, hi;
            lo.x = acc[ti][j][0] + bx; lo.y = acc[ti][j][1] + by;
            hi.x = acc[ti][j][2] + bx; hi.y = acc[ti][j][3] + by;
            *reinterpret_cast<float2*>(&C[(size_t)r0 * Ncols + c0]) = lo;
            *reinterpret_cast<float2*>(&C[(size_t)(r0+8) * Ncols + c0]) = hi;
        }
    }
}

// ============================================================
// Normalize + scatter. Now also pre-splits q,k into tf32 hi/lo
// (interleaved, matching flash smem rows) and pre-rounds v.
// ============================================================
__global__ __launch_bounds__(256)
void norm_scatter_kernel(const float* __restrict__ logit_scale) {
    const int warp = (blockIdx.x * blockDim.x + threadIdx.x) >> 5;
    const int lane = threadIdx.x & 31;
    const int tsel = warp / (NHH * LL);
    const int rr   = warp - tsel * (NHH * LL);
    const int nh   = rr >> 10;
    const int l    = rr & 1023;
    const int n    = nh >> 4;
    const int h    = nh & 15;
    const size_t src = (size_t)(l * NB + n) * C3 + (size_t)tsel * CC + h * HD;
    float v0 = g_qkv[src + lane];
    float v1 = g_qkv[src + lane + 32];
    if (tsel < 2) {
        float s = v0*v0 + v1*v1;
        #pragma unroll
        for (int o = 16; o > 0; o >>= 1) s += __shfl_xor_sync(0xffffffffu, s, o);
        float inv = 1.0f / fmaxf(sqrtf(s), 1e-12f);
        if (tsel == 0) inv *= expf(fminf(logit_scale[h], LOGIT_MAX));
        v0 *= inv; v1 *= inv;
        float h0 = tf32r(v0), h1 = tf32r(v1);
        float2* dst = reinterpret_cast<float2*>(tsel == 0 ? g_q : g_k)
                      + ((size_t)nh * LL + l) * 64;
        dst[lane]      = make_float2(h0, tf32r(v0 - h0));
        dst[lane + 32] = make_float2(h1, tf32r(v1 - h1));
    } else {
        const size_t o = ((size_t)nh * LL + l) * HD;
        g_v[o + lane]      = tf32r(v0);
        g_v[o + lane + 32] = tf32r(v1);
    }
}

// ============================================================
// Flash attention, tf32 mma. Loader is now pure cp.async
// (operands pre-split/pre-rounded in gmem). Compute unchanged.
// ============================================================
#define QKSTR 132
#define VSTR  72
#define PSTR  72
#define FL_Q 0
#define FL_K (64*QKSTR)
#define FL_V (2*64*QKSTR)
#define FL_P (2*64*QKSTR + 64*VSTR)
#define FLASH_SMEM ((2*64*QKSTR + 64*VSTR + 64*PSTR) * (int)sizeof(float))

__global__ __launch_bounds__(128, 2)
void flash_attn_mma(const float* __restrict__ head_scale) {
    extern __shared__ float smf[];
    float* Qs = smf + FL_Q;
    float* Ks = smf + FL_K;
    float* Vs = smf + FL_V;
    float* Ps = smf + FL_P;
    const uint32_t smbQ = smem_u32(smf) + FL_Q * 4;
    const uint32_t smbK = smem_u32(smf) + FL_K * 4;
    const uint32_t smbV = smem_u32(smf) + FL_V * 4;

    const int t    = threadIdx.x;
    const int w    = t >> 5;
    const int lane = t & 31;
    const int g    = lane >> 2;
    const int kq   = lane & 3;
    const int nh = blockIdx.y;
    const int qt = blockIdx.x;
    const float* Qg = g_q + ((size_t)nh * LL + qt * 64) * 128;
    const float* Kg = g_k + (size_t)nh * LL * 128;
    const float* Vg = g_v + (size_t)nh * LL * HD;

    // Q tile: 64 rows x 128 floats (hi/lo interleaved), smem row stride 132
    for (int i = t; i < 2048; i += 128) {
        int r = i >> 5, c = i & 31;
        cp16(smbQ + r*(QKSTR*4) + c*16, Qg + r*128 + c*4);
    }

    float acc[8][4] = {};
    float miA = -1e30f, miB = -1e30f, liA = 0.0f, liB = 0.0f;

    const int rA = w*16 + g;
    const int rB = rA + 8;

    for (int kt = 0; kt < 16; kt++) {
        const float* Kt = Kg + (size_t)kt * 64 * 128;
        const float* Vt = Vg + (size_t)kt * 64 * 64;
        for (int i = t; i < 2048; i += 128) {
            int r = i >> 5, c = i & 31;
            cp16(smbK + r*(QKSTR*4) + c*16, Kt + r*128 + c*4);
        }
        for (int i = t; i < 1024; i += 128) {
            int r = i >> 4, c = i & 15;
            cp16(smbV + r*(VSTR*4) + c*16, Vt + r*64 + c*4);
        }
        cp_commit();
        cp_wait0();
        __syncthreads();

        float sd[8][4] = {};
        #pragma unroll
        for (int kb = 0; kb < 8; kb++) {
            const float2* qr0 = reinterpret_cast<const float2*>(&Qs[rA*QKSTR]);
            const float2* qr1 = reinterpret_cast<const float2*>(&Qs[rB*QKSTR]);
            float2 a0 = qr0[kb*8+kq],   a1 = qr1[kb*8+kq];
            float2 a2 = qr0[kb*8+kq+4], a3 = qr1[kb*8+kq+4];
            uint32_t ahi[4] = {__float_as_uint(a0.x), __float_as_uint(a1.x),
                               __float_as_uint(a2.x), __float_as_uint(a3.x)};
            uint32_t alo[4] = {__float_as_uint(a0.y), __float_as_uint(a1.y),
                               __float_as_uint(a2.y), __float_as_uint(a3.y)};
            #pragma unroll
            for (int j = 0; j < 8; j++) {
                const float2* kr = reinterpret_cast<const float2*>(&Ks[(j*8+g)*QKSTR]);
                float2 b0 = kr[kb*8+kq], b1 = kr[kb*8+kq+4];
                uint32_t bhi[2] = {__float_as_uint(b0.x), __float_as_uint(b1.x)};
                uint32_t blo[2] = {__float_as_uint(b0.y), __float_as_uint(b1.y)};
                mma_tf32_16x8x8(sd[j], ahi, bhi);
                mma_tf32_16x8x8(sd[j], ahi, blo);
                mma_tf32_16x8x8(sd[j], alo, bhi);
            }
        }

        float rmA = -1e30f, rmB = -1e30f;
        #pragma unroll
        for (int j = 0; j < 8; j++) {
            rmA = fmaxf(rmA, fmaxf(sd[j][0], sd[j][1]));
            rmB = fmaxf(rmB, fmaxf(sd[j][2], sd[j][3]));
        }
        rmA = fmaxf(rmA, __shfl_xor_sync(0xffffffffu, rmA, 1));
        rmA = fmaxf(rmA, __shfl_xor_sync(0xffffffffu, rmA, 2));
        rmB = fmaxf(rmB, __shfl_xor_sync(0xffffffffu, rmB, 1));
        rmB = fmaxf(rmB, __shfl_xor_sync(0xffffffffu, rmB, 2));
        float mA = fmaxf(miA, rmA), mB = fmaxf(miB, rmB);
        float corrA = __expf(miA - mA), corrB = __expf(miB - mB);
        float sumA = 0.0f, sumB = 0.0f;
        #pragma unroll
        for (int j = 0; j < 8; j++) {
            float p0 = __expf(sd[j][0] - mA);
            float p1 = __expf(sd[j][1] - mA);
            float p2 = __expf(sd[j][2] - mB);
            float p3 = __expf(sd[j][3] - mB);
            sumA += p0 + p1;
            sumB += p2 + p3;
            *reinterpret_cast<float2*>(&Ps[rA*PSTR + j*8 + 2*kq]) =
                make_float2(tf32r(p0), tf32r(p1));
            *reinterpret_cast<float2*>(&Ps[rB*PSTR + j*8 + 2*kq]) =
                make_float2(tf32r(p2), tf32r(p3));
            acc[j][0] *= corrA; acc[j][1] *= corrA;
            acc[j][2] *= corrB; acc[j][3] *= corrB;
        }
        sumA += __shfl_xor_sync(0xffffffffu, sumA, 1);
        sumA += __shfl_xor_sync(0xffffffffu, sumA, 2);
        sumB += __shfl_xor_sync(0xffffffffu, sumB, 1);
        sumB += __shfl_xor_sync(0xffffffffu, sumB, 2);
        liA = liA * corrA + sumA;  miA = mA;
        liB = liB * corrB + sumB;  miB = mB;
        __syncwarp();

        #pragma unroll
        for (int kb = 0; kb < 8; kb++) {
            uint32_t pa[4];
            pa[0] = __float_as_uint(Ps[rA*PSTR + kb*8+kq]);
            pa[1] = __float_as_uint(Ps[rB*PSTR + kb*8+kq]);
            pa[2] = __float_as_uint(Ps[rA*PSTR + kb*8+kq+4]);
            pa[3] = __float_as_uint(Ps[rB*PSTR + kb*8+kq+4]);
            #pragma unroll
            for (int j = 0; j < 8; j++) {
                uint32_t vb[2];
                vb[0] = __float_as_uint(Vs[(kb*8+kq)*VSTR   + j*8+g]);
                vb[1] = __float_as_uint(Vs[(kb*8+kq+4)*VSTR + j*8+g]);
                mma_tf32_16x8x8(acc[j], pa, vb);
            }
        }
        __syncthreads();
    }

    const int h = nh & 15;
    const int n = nh >> 4;
    const float hs = head_scale[h];
    const float sAf = hs / liA, sBf = hs / liB;
    const int lA = qt*64 + rA;
    const int lB = qt*64 + rB;
    #pragma unroll
    for (int j = 0; j < 8; j++) {
        const int col = h*HD + j*8 + 2*kq;
        *reinterpret_cast<float2*>(&g_o[(size_t)(lA*NB + n)*CC + col]) =
            make_float2(acc[j][0]*sAf, acc[j][1]*sAf);
        *reinterpret_cast<float2*>(&g_o[(size_t)(lB*NB + n)*CC + col]) =
            make_float2(acc[j][2]*sBf, acc[j][3]*sBf);
    }
}

// ============================================================
extern "C" void kernel_launch(void* const* d_in, const int* in_sizes, int n_in,
                              void* d_out, int out_size) {
    const float* x           = (const float*)d_in[0];
    const float* w_in        = (const float*)d_in[1];
    const float* b_in        = (const float*)d_in[2];
    const float* logit_scale = (const float*)d_in[3];
    const float* head_scale  = (const float*)d_in[4];
    const float* out_w       = (const float*)d_in[5];
    const float* out_b       = (const float*)d_in[6];
    float* out = (float*)d_out;

    float *qkv_p, *o_p, *xp_p, *op_p, *w1p_p, *w2p_p;
    cudaGetSymbolAddress((void**)&qkv_p, g_qkv);
    cudaGetSymbolAddress((void**)&o_p,   g_o);
    cudaGetSymbolAddress((void**)&xp_p,  g_xp);
    cudaGetSymbolAddress((void**)&op_p,  g_op);
    cudaGetSymbolAddress((void**)&w1p_p, g_w1p);
    cudaGetSymbolAddress((void**)&w2p_p, g_w2p);

    cudaFuncSetAttribute(flash_attn_mma,
                         cudaFuncAttributeMaxDynamicSharedMemorySize, FLASH_SMEM);
    cudaFuncSetAttribute(gemm_tf32_pk,
                         cudaFuncAttributeMaxDynamicSharedMemorySize, GEMM_SMEM);

    pack_a<<<MM, 256>>>(x, xp_p);
    pack_b<<<C3*2, 256>>>(w_in, w1p_p);
    pack_b<<<CC*2, 256>>>(out_w, w2p_p);

    // 1) qkv = x @ W^T + b
    gemm_tf32_pk<<<dim3(C3/128, MM/128), 256, GEMM_SMEM>>>(xp_p, w1p_p, b_in, qkv_p, C3);
    // 2) normalize + scatter (+ hi/lo split, tf32 pre-round)
    norm_scatter_kernel<<<(3*NHH*LL)/8, 256>>>(logit_scale);
    // 3) flash attention
    flash_attn_mma<<<dim3(LL/64, NHH), 128, FLASH_SMEM>>>(head_scale);
    // 4) out = o @ out_w^T + out_b
    pack_a<<<MM, 256>>>(o_p, op_p);
    gemm_tf32_pk<<<dim3(CC/128, MM/128), 256, GEMM_SMEM>>>(op_p, w2p_p, out_b, out, CC);
}